// round 8
// baseline (speedup 1.0000x reference)
#include <cuda_runtime.h>
#include <cuda_bf16.h>
#include <cstdint>
#include <math.h>

// Fixed problem sizes
#define M_TOTAL 8192      // B*S = 4*2048
#define N_TOTAL 4096      // OUT
#define K_TOTAL 4096      // IN

// ---- device-global scratch (allocation-free) ----
__device__ __align__(16) int8_t g_xq[(size_t)M_TOTAL * K_TOTAL];  // quantized x
__device__ __align__(16) int8_t g_cb[(size_t)N_TOTAL * K_TOTAL];  // normalized int8 weights
__device__ float g_sx[M_TOTAL];                                   // per-row scale absmax/127
__device__ int   g_cb_mode;   // 0=int8 packed, 1=int32, 2=fp32, 3=bf16

// ============================================================================
// Kernel 0a: detect the true storage dtype of CB.
// Samples the first 4096 elements under each interpretation. All sampled
// reads stay within the first 16KB (buffer is >= 16MB in every case).
// Priority: int32 > fp32 > bf16 > int8. Each test requires ALL 4096 samples
// to look like small integers in [-127,127] — decisive for true layout,
// astronomically unlikely for a wrong one.
// ============================================================================
__global__ void detect_cb_kernel(const void* __restrict__ cb) {
    __shared__ int ok_i32, ok_f32, ok_bf16;
    if (threadIdx.x == 0) { ok_i32 = 1; ok_f32 = 1; ok_bf16 = 1; }
    __syncthreads();

    const int tid = threadIdx.x;
    bool my_i32 = true, my_f32 = true, my_bf16 = true;
#pragma unroll
    for (int t = 0; t < 16; t++) {
        const int idx = tid + t * 256;          // 0..4095
        // int32 interpretation
        const int vi = ((const int*)cb)[idx];
        if (vi < -127 || vi > 127) my_i32 = false;
        // fp32 interpretation
        const float vf = ((const float*)cb)[idx];
        if (!(isfinite(vf) && fabsf(vf) <= 127.0f && vf == rintf(vf))) my_f32 = false;
        // bf16 interpretation
        const unsigned short h = ((const unsigned short*)cb)[idx];
        __nv_bfloat16 bh = *reinterpret_cast<const __nv_bfloat16*>(&h);
        const float vb = __bfloat162float(bh);
        if (!(isfinite(vb) && fabsf(vb) <= 127.0f && vb == rintf(vb))) my_bf16 = false;
    }
    if (!my_i32)  ok_i32 = 0;    // benign race: only 0 is ever written
    if (!my_f32)  ok_f32 = 0;
    if (!my_bf16) ok_bf16 = 0;
    __syncthreads();

    if (tid == 0) {
        int mode = 0;                 // default: packed int8
        if      (ok_i32)  mode = 1;
        else if (ok_f32)  mode = 2;
        else if (ok_bf16) mode = 3;
        g_cb_mode = mode;
    }
}

// ============================================================================
// Kernel 0b: normalize CB into packed int8 (g_cb). Each thread handles 4
// elements. Wide reads are guarded by the runtime mode flag, so no read ever
// exceeds the actual buffer extent.
// ============================================================================
__global__ __launch_bounds__(256) void convert_cb_kernel(const void* __restrict__ cb) {
    const int mode = g_cb_mode;
    const size_t q = (size_t)blockIdx.x * 256 + threadIdx.x;  // quad index
    // total quads = 16,777,216 / 4 = 4,194,304
    int* dst = reinterpret_cast<int*>(g_cb);

    if (mode == 0) {
        // already packed int8: straight 4-byte copy
        dst[q] = ((const int*)cb)[q];
    } else if (mode == 1) {
        const int4 v = ((const int4*)cb)[q];
        const unsigned r = (unsigned)(v.x & 0xff)        |
                           ((unsigned)(v.y & 0xff) << 8) |
                           ((unsigned)(v.z & 0xff) << 16)|
                           ((unsigned)(v.w & 0xff) << 24);
        dst[q] = (int)r;
    } else if (mode == 2) {
        const float4 v = ((const float4*)cb)[q];
        const int a = __float2int_rn(v.x) & 0xff;
        const int b = __float2int_rn(v.y) & 0xff;
        const int c = __float2int_rn(v.z) & 0xff;
        const int d = __float2int_rn(v.w) & 0xff;
        dst[q] = a | (b << 8) | (c << 16) | (d << 24);
    } else {
        const __nv_bfloat162* p = reinterpret_cast<const __nv_bfloat162*>(cb);
        const __nv_bfloat162 v0 = p[q * 2], v1 = p[q * 2 + 1];
        const int a = __float2int_rn(__bfloat162float(v0.x)) & 0xff;
        const int b = __float2int_rn(__bfloat162float(v0.y)) & 0xff;
        const int c = __float2int_rn(__bfloat162float(v1.x)) & 0xff;
        const int d = __float2int_rn(__bfloat162float(v1.y)) & 0xff;
        dst[q] = a | (b << 8) | (c << 16) | (d << 24);
    }
}

// ============================================================================
// Kernel 1: per-row dynamic int8 quantization of x. One 256-thread block/row.
// __float2int_rn (round-half-even) matches jnp.round; IEEE divide matches x/sx.
// ============================================================================
__global__ __launch_bounds__(256) void quant_v2(const float* __restrict__ x) {
    __shared__ float smax[256];
    const int row = blockIdx.x;
    const int tid = threadIdx.x;
    const float* xr = x + (size_t)row * K_TOTAL;

    float v[16];
    float am = 0.0f;
#pragma unroll
    for (int t = 0; t < 16; t++) {
        v[t] = xr[tid + t * 256];
        am = fmaxf(am, fabsf(v[t]));
    }
    smax[tid] = am;
    __syncthreads();
#pragma unroll
    for (int off = 128; off > 0; off >>= 1) {
        if (tid < off) smax[tid] = fmaxf(smax[tid], smax[tid + off]);
        __syncthreads();
    }
    const float s = smax[0] / 127.0f;

    int8_t* q = g_xq + (size_t)row * K_TOTAL;
#pragma unroll
    for (int t = 0; t < 16; t++) {
        q[tid + t * 256] = (int8_t)__float2int_rn(v[t] / s);
    }
    if (tid == 0) g_sx[row] = s;
}

// ============================================================================
// Kernel 2: int8 NT GEMM via dp4a, int32 accumulate, fused dequant epilogue:
//     y[m,n] = float(acc) * sx[m] * (SCB[n] / 127)
// 128x128 tile, 64B K-tile, 256 threads, 8x8 micro-tile, XOR-swizzled SMEM.
// ============================================================================
#define BM 128
#define BN 128
#define KW 16          // int words per K-tile (64 bytes)

__global__ __launch_bounds__(256) void gemm_v2(const float* __restrict__ SCB,
                                               float* __restrict__ y) {
    __shared__ int As[BM * KW];
    __shared__ int Bs[BN * KW];

    const int tid = threadIdx.x;
    const int bn = blockIdx.x;
    const int bm = blockIdx.y;

    const int r0 = tid >> 2;          // 0..63
    const int s0 = tid & 3;           // 16B segment of the 64B slab
    const int r1 = r0 + 64;

    const int8_t* aP0 = g_xq + (size_t)(bm * BM + r0) * K_TOTAL + s0 * 16;
    const int8_t* aP1 = g_xq + (size_t)(bm * BM + r1) * K_TOTAL + s0 * 16;
    const int8_t* bP0 = g_cb + (size_t)(bn * BN + r0) * K_TOTAL + s0 * 16;
    const int8_t* bP1 = g_cb + (size_t)(bn * BN + r1) * K_TOTAL + s0 * 16;

    int acc[8][8];
#pragma unroll
    for (int i = 0; i < 8; i++)
#pragma unroll
        for (int j = 0; j < 8; j++) acc[i][j] = 0;

    const int ty = tid >> 4;
    const int tx = tid & 15;
    const int sw0 = r0 >> 3;
    const int sw1 = r1 >> 3;

    for (int kt = 0; kt < K_TOTAL / 64; kt++) {
        const int4 a0 = *reinterpret_cast<const int4*>(aP0 + kt * 64);
        const int4 a1 = *reinterpret_cast<const int4*>(aP1 + kt * 64);
        const int4 b0 = *reinterpret_cast<const int4*>(bP0 + kt * 64);
        const int4 b1 = *reinterpret_cast<const int4*>(bP1 + kt * 64);

        __syncthreads();

        As[r0 * KW + ((s0 * 4 + 0) ^ sw0)] = a0.x;
        As[r0 * KW + ((s0 * 4 + 1) ^ sw0)] = a0.y;
        As[r0 * KW + ((s0 * 4 + 2) ^ sw0)] = a0.z;
        As[r0 * KW + ((s0 * 4 + 3) ^ sw0)] = a0.w;
        As[r1 * KW + ((s0 * 4 + 0) ^ sw1)] = a1.x;
        As[r1 * KW + ((s0 * 4 + 1) ^ sw1)] = a1.y;
        As[r1 * KW + ((s0 * 4 + 2) ^ sw1)] = a1.z;
        As[r1 * KW + ((s0 * 4 + 3) ^ sw1)] = a1.w;
        Bs[r0 * KW + ((s0 * 4 + 0) ^ sw0)] = b0.x;
        Bs[r0 * KW + ((s0 * 4 + 1) ^ sw0)] = b0.y;
        Bs[r0 * KW + ((s0 * 4 + 2) ^ sw0)] = b0.z;
        Bs[r0 * KW + ((s0 * 4 + 3) ^ sw0)] = b0.w;
        Bs[r1 * KW + ((s0 * 4 + 0) ^ sw1)] = b1.x;
        Bs[r1 * KW + ((s0 * 4 + 1) ^ sw1)] = b1.y;
        Bs[r1 * KW + ((s0 * 4 + 2) ^ sw1)] = b1.z;
        Bs[r1 * KW + ((s0 * 4 + 3) ^ sw1)] = b1.w;

        __syncthreads();

#pragma unroll
        for (int kw = 0; kw < KW; kw++) {
            int a[8], b[8];
#pragma unroll
            for (int i = 0; i < 8; i++)
                a[i] = As[(ty * 8 + i) * KW + (kw ^ ty)];
#pragma unroll
            for (int j = 0; j < 8; j++)
                b[j] = Bs[(tx * 8 + j) * KW + (kw ^ tx)];
#pragma unroll
            for (int i = 0; i < 8; i++)
#pragma unroll
                for (int j = 0; j < 8; j++)
                    acc[i][j] = __dp4a(a[i], b[j], acc[i][j]);
        }
    }

    const int m0 = bm * BM + ty * 8;
    const int n0 = bn * BN + tx * 8;
#pragma unroll
    for (int i = 0; i < 8; i++) {
        const float sm = g_sx[m0 + i];
        float* yr = y + (size_t)(m0 + i) * N_TOTAL;
#pragma unroll
        for (int j = 0; j < 8; j++) {
            yr[n0 + j] = ((float)acc[i][j] * sm) * (SCB[n0 + j] * (1.0f / 127.0f));
        }
    }
}

// ============================================================================
// Launch. Inputs bound by element count:
//   x: 33,554,432 (fp32)   CB: 16,777,216 (dtype unknown -> detected)
//   SCB: 4,096 (fp32)
// ============================================================================
extern "C" void kernel_launch(void* const* d_in, const int* in_sizes, int n_in,
                              void* d_out, int out_size) {
    const float* x   = nullptr;
    const void*  CB  = nullptr;
    const float* SCB = nullptr;

    for (int i = 0; i < n_in; i++) {
        if (in_sizes[i] == 33554432)      x   = (const float*)d_in[i];
        else if (in_sizes[i] == 16777216) CB  = d_in[i];
        else if (in_sizes[i] == 4096)     SCB = (const float*)d_in[i];
    }

    float* y = (float*)d_out;

    detect_cb_kernel<<<1, 256>>>(CB);
    convert_cb_kernel<<<(N_TOTAL * K_TOTAL / 4) / 256, 256>>>(CB);  // 16384 blocks
    quant_v2<<<M_TOTAL, 256>>>(x);
    dim3 grid(N_TOTAL / BN, M_TOTAL / BM);
    gemm_v2<<<grid, 256>>>(SCB, y);
}

// round 11
// speedup vs baseline: 1.2106x; 1.2106x over previous
#include <cuda_runtime.h>
#include <cuda_bf16.h>
#include <cstdint>
#include <math.h>

// Fixed problem sizes
#define M_TOTAL 8192      // B*S = 4*2048
#define N_TOTAL 4096      // OUT
#define K_TOTAL 4096      // IN

// ---- device-global scratch (allocation-free) ----
__device__ __align__(16) int8_t g_xq[(size_t)M_TOTAL * K_TOTAL];  // quantized x
__device__ __align__(16) int8_t g_cb[(size_t)N_TOTAL * K_TOTAL];  // normalized int8 weights
__device__ float g_sx[M_TOTAL];                                   // per-row scale absmax/127
__device__ int   g_cb_mode;   // 0=int8 packed, 1=int32, 2=fp32, 3=bf16

// ============================================================================
// Helpers (base-ISA only: ldmatrix + mma.sync are NOT 'a'-gated)
// ============================================================================
__device__ __forceinline__ uint32_t smem_u32(const void* p) {
    uint32_t a;
    asm("{ .reg .u64 t; cvta.to.shared.u64 t, %1; cvt.u32.u64 %0, t; }"
        : "=r"(a) : "l"(p));
    return a;
}
__device__ __forceinline__ void sts128(uint32_t addr, int4 v) {
    asm volatile("st.shared.v4.b32 [%0], {%1, %2, %3, %4};"
                 :: "r"(addr), "r"(v.x), "r"(v.y), "r"(v.z), "r"(v.w) : "memory");
}
__device__ __forceinline__ void ldsm_x4(uint32_t* r, uint32_t addr) {
    asm volatile("ldmatrix.sync.aligned.m8n8.x4.shared.b16 {%0,%1,%2,%3}, [%4];"
                 : "=r"(r[0]), "=r"(r[1]), "=r"(r[2]), "=r"(r[3]) : "r"(addr));
}
__device__ __forceinline__ void mma_s8(int* c, const uint32_t* a, const uint32_t* b) {
    asm volatile("mma.sync.aligned.m16n8k32.row.col.s32.s8.s8.s32 "
                 "{%0,%1,%2,%3}, {%4,%5,%6,%7}, {%8,%9}, {%0,%1,%2,%3};"
                 : "+r"(c[0]), "+r"(c[1]), "+r"(c[2]), "+r"(c[3])
                 : "r"(a[0]), "r"(a[1]), "r"(a[2]), "r"(a[3]),
                   "r"(b[0]), "r"(b[1]));
}
// Swizzled byte offset for a [128 x 64B] tile: XOR 16B-chunk bits[4:6] with
// row-pair bits ((row>>1)&7). Conflict-free for ldmatrix 8-address groups
// and for the producer's STS pattern. k < 64.
__device__ __forceinline__ uint32_t swoff(int row, int k) {
    return (uint32_t)(row * 64 + k) ^ (((((uint32_t)row) >> 1) & 7u) << 4);
}

// ============================================================================
// Kernel 0a: detect CB storage dtype (unchanged, proven in R8)
// ============================================================================
__global__ void detect_cb_kernel(const void* __restrict__ cb) {
    __shared__ int ok_i32, ok_f32, ok_bf16;
    if (threadIdx.x == 0) { ok_i32 = 1; ok_f32 = 1; ok_bf16 = 1; }
    __syncthreads();
    const int tid = threadIdx.x;
    bool my_i32 = true, my_f32 = true, my_bf16 = true;
#pragma unroll
    for (int t = 0; t < 16; t++) {
        const int idx = tid + t * 256;
        const int vi = ((const int*)cb)[idx];
        if (vi < -127 || vi > 127) my_i32 = false;
        const float vf = ((const float*)cb)[idx];
        if (!(isfinite(vf) && fabsf(vf) <= 127.0f && vf == rintf(vf))) my_f32 = false;
        const unsigned short h = ((const unsigned short*)cb)[idx];
        __nv_bfloat16 bh = *reinterpret_cast<const __nv_bfloat16*>(&h);
        const float vb = __bfloat162float(bh);
        if (!(isfinite(vb) && fabsf(vb) <= 127.0f && vb == rintf(vb))) my_bf16 = false;
    }
    if (!my_i32)  ok_i32 = 0;
    if (!my_f32)  ok_f32 = 0;
    if (!my_bf16) ok_bf16 = 0;
    __syncthreads();
    if (tid == 0) {
        int mode = 0;
        if      (ok_i32)  mode = 1;
        else if (ok_f32)  mode = 2;
        else if (ok_bf16) mode = 3;
        g_cb_mode = mode;
    }
}

// ============================================================================
// Kernel 0b: normalize CB into packed int8 (unchanged)
// ============================================================================
__global__ __launch_bounds__(256) void convert_cb_kernel(const void* __restrict__ cb) {
    const int mode = g_cb_mode;
    const size_t q = (size_t)blockIdx.x * 256 + threadIdx.x;
    int* dst = reinterpret_cast<int*>(g_cb);
    if (mode == 0) {
        dst[q] = ((const int*)cb)[q];
    } else if (mode == 1) {
        const int4 v = ((const int4*)cb)[q];
        dst[q] = (int)((unsigned)(v.x & 0xff) | ((unsigned)(v.y & 0xff) << 8) |
                       ((unsigned)(v.z & 0xff) << 16) | ((unsigned)(v.w & 0xff) << 24));
    } else if (mode == 2) {
        const float4 v = ((const float4*)cb)[q];
        const int a = __float2int_rn(v.x) & 0xff, b = __float2int_rn(v.y) & 0xff;
        const int c = __float2int_rn(v.z) & 0xff, d = __float2int_rn(v.w) & 0xff;
        dst[q] = a | (b << 8) | (c << 16) | (d << 24);
    } else {
        const __nv_bfloat162* p = reinterpret_cast<const __nv_bfloat162*>(cb);
        const __nv_bfloat162 v0 = p[q * 2], v1 = p[q * 2 + 1];
        const int a = __float2int_rn(__bfloat162float(v0.x)) & 0xff;
        const int b = __float2int_rn(__bfloat162float(v0.y)) & 0xff;
        const int c = __float2int_rn(__bfloat162float(v1.x)) & 0xff;
        const int d = __float2int_rn(__bfloat162float(v1.y)) & 0xff;
        dst[q] = a | (b << 8) | (c << 16) | (d << 24);
    }
}

// ============================================================================
// Kernel 1: per-row dynamic int8 quantization of x (unchanged)
// ============================================================================
__global__ __launch_bounds__(256) void quant_v2(const float* __restrict__ x) {
    __shared__ float smax[256];
    const int row = blockIdx.x;
    const int tid = threadIdx.x;
    const float* xr = x + (size_t)row * K_TOTAL;
    float v[16];
    float am = 0.0f;
#pragma unroll
    for (int t = 0; t < 16; t++) {
        v[t] = xr[tid + t * 256];
        am = fmaxf(am, fabsf(v[t]));
    }
    smax[tid] = am;
    __syncthreads();
#pragma unroll
    for (int off = 128; off > 0; off >>= 1) {
        if (tid < off) smax[tid] = fmaxf(smax[tid], smax[tid + off]);
        __syncthreads();
    }
    const float s = smax[0] / 127.0f;
    int8_t* q = g_xq + (size_t)row * K_TOTAL;
#pragma unroll
    for (int t = 0; t < 16; t++) q[tid + t * 256] = (int8_t)__float2int_rn(v[t] / s);
    if (tid == 0) g_sx[row] = s;
}

// ============================================================================
// Kernel 2: int8 tensor-core GEMM via mma.sync.m16n8k32 (base ISA, sm_80+).
// 128x128 CTA tile, BK=64B K-slab, 8 warps in 2x4 (warp tile 64x32).
// Double-buffered swizzled SMEM; register prefetch of next slab.
// Epilogue: y[m,n] = acc * sx[m] * (SCB[n]/127).
// ============================================================================
#define BK 64

__global__ __launch_bounds__(256) void gemm_imma(const float* __restrict__ SCB,
                                                 float* __restrict__ y) {
    __shared__ int8_t As[2][128 * BK];   // 2 x 8 KB
    __shared__ int8_t Bs[2][128 * BK];   // 2 x 8 KB

    const int tid = threadIdx.x;
    const int wid = tid >> 5;
    const int lane = tid & 31;
    const int bn = blockIdx.x;     // N tile (0..31)
    const int bm = blockIdx.y;     // M tile (0..63)
    const int wm = wid >> 2;       // 0..1  -> m offset wm*64
    const int wn = wid & 3;        // 0..3  -> n offset wn*32

    // ---- producer mapping: 512 16B-chunks per operand; 2 per thread ----
    const int pr0 = tid >> 2;      // rows 0..63
    const int pseg = tid & 3;      // 16B segment within 64B slab
    const int pr1 = pr0 + 64;
    const int8_t* aG0 = g_xq + (size_t)(bm * 128 + pr0) * K_TOTAL + pseg * 16;
    const int8_t* aG1 = g_xq + (size_t)(bm * 128 + pr1) * K_TOTAL + pseg * 16;
    const int8_t* bG0 = g_cb + (size_t)(bn * 128 + pr0) * K_TOTAL + pseg * 16;
    const int8_t* bG1 = g_cb + (size_t)(bn * 128 + pr1) * K_TOTAL + pseg * 16;
    const uint32_t so0 = swoff(pr0, pseg * 16);
    const uint32_t so1 = swoff(pr1, pseg * 16);

    const uint32_t aSm = smem_u32(&As[0][0]);
    const uint32_t bSm = smem_u32(&Bs[0][0]);

    // ---- ldmatrix lane geometry ----
    // A (x4): lanes 0-7: rows m0..+7 k0 | 8-15: rows +8 k0 | 16-23: rows +0 k16 | 24-31: rows +8 k16
    // B (x4): lanes 0-7: rows n0..+7 k0 | 8-15: rows +0 k16 | 16-23: rows +8 k0 | 24-31: rows +8 k16
    const int q = lane >> 3, lr = lane & 7;
    const int aRowL = wm * 64 + (q & 1) * 8 + lr;   // + fi*16
    const int aKL   = (q >> 1) * 16;
    const int bRowL = wn * 32 + (q >> 1) * 8 + lr;  // + pair*16
    const int bKL   = (q & 1) * 16;

    int acc[16][4];
#pragma unroll
    for (int f = 0; f < 16; f++)
#pragma unroll
        for (int r = 0; r < 4; r++) acc[f][r] = 0;

    // ---- preload tile 0 ----
    int4 ra0 = *reinterpret_cast<const int4*>(aG0);
    int4 ra1 = *reinterpret_cast<const int4*>(aG1);
    int4 rb0 = *reinterpret_cast<const int4*>(bG0);
    int4 rb1 = *reinterpret_cast<const int4*>(bG1);
    sts128(aSm + so0, ra0); sts128(aSm + so1, ra1);
    sts128(bSm + so0, rb0); sts128(bSm + so1, rb1);
    __syncthreads();

    const int NT = K_TOTAL / BK;   // 64
    for (int kt = 0; kt < NT; kt++) {
        const int buf = kt & 1;
        if (kt + 1 < NT) {   // prefetch next slab under compute
            ra0 = *reinterpret_cast<const int4*>(aG0 + (kt + 1) * BK);
            ra1 = *reinterpret_cast<const int4*>(aG1 + (kt + 1) * BK);
            rb0 = *reinterpret_cast<const int4*>(bG0 + (kt + 1) * BK);
            rb1 = *reinterpret_cast<const int4*>(bG1 + (kt + 1) * BK);
        }
        const uint32_t aB = aSm + buf * (128 * BK);
        const uint32_t bB = bSm + buf * (128 * BK);

#pragma unroll
        for (int ks = 0; ks < 2; ks++) {      // two K=32 steps per 64B slab
            uint32_t a[4][4], b[4][2];
#pragma unroll
            for (int fi = 0; fi < 4; fi++)
                ldsm_x4(a[fi], aB + swoff(aRowL + fi * 16, aKL + ks * 32));
#pragma unroll
            for (int pr = 0; pr < 2; pr++) {
                uint32_t t4[4];
                ldsm_x4(t4, bB + swoff(bRowL + pr * 16, bKL + ks * 32));
                b[pr * 2][0] = t4[0]; b[pr * 2][1] = t4[1];
                b[pr * 2 + 1][0] = t4[2]; b[pr * 2 + 1][1] = t4[3];
            }
#pragma unroll
            for (int fi = 0; fi < 4; fi++)
#pragma unroll
                for (int fj = 0; fj < 4; fj++)
                    mma_s8(acc[fi * 4 + fj], a[fi], b[fj]);
        }

        __syncthreads();
        if (kt + 1 < NT) {
            const uint32_t aN = aSm + (buf ^ 1) * (128 * BK);
            const uint32_t bN = bSm + (buf ^ 1) * (128 * BK);
            sts128(aN + so0, ra0); sts128(aN + so1, ra1);
            sts128(bN + so0, rb0); sts128(bN + so1, rb1);
        }
        __syncthreads();
    }

    // ---- epilogue: dequant + store ----
    const int g = lane >> 2, tg = lane & 3;
    float scb[8];
#pragma unroll
    for (int fj = 0; fj < 4; fj++) {
        const int n = bn * 128 + wn * 32 + fj * 8 + tg * 2;
        scb[fj * 2]     = SCB[n]     * (1.0f / 127.0f);
        scb[fj * 2 + 1] = SCB[n + 1] * (1.0f / 127.0f);
    }
#pragma unroll
    for (int fi = 0; fi < 4; fi++) {
#pragma unroll
        for (int h = 0; h < 2; h++) {
            const int m = bm * 128 + wm * 64 + fi * 16 + g + h * 8;
            const float sm = g_sx[m];
            float* yr = y + (size_t)m * N_TOTAL + bn * 128 + wn * 32;
#pragma unroll
            for (int fj = 0; fj < 4; fj++) {
                const int* c = acc[fi * 4 + fj];
                float2 o;
                o.x = (float)c[h * 2]     * sm * scb[fj * 2];
                o.y = (float)c[h * 2 + 1] * sm * scb[fj * 2 + 1];
                *reinterpret_cast<float2*>(yr + fj * 8 + tg * 2) = o;
            }
        }
    }
}

// ============================================================================
// Launch. Inputs bound by element count:
//   x: 33,554,432   CB: 16,777,216 (dtype auto-detected)   SCB: 4,096
// ============================================================================
extern "C" void kernel_launch(void* const* d_in, const int* in_sizes, int n_in,
                              void* d_out, int out_size) {
    const float* x   = nullptr;
    const void*  CB  = nullptr;
    const float* SCB = nullptr;
    for (int i = 0; i < n_in; i++) {
        if (in_sizes[i] == 33554432)      x   = (const float*)d_in[i];
        else if (in_sizes[i] == 16777216) CB  = d_in[i];
        else if (in_sizes[i] == 4096)     SCB = (const float*)d_in[i];
    }
    float* y = (float*)d_out;

    detect_cb_kernel<<<1, 256>>>(CB);
    convert_cb_kernel<<<(N_TOTAL * K_TOTAL / 4) / 256, 256>>>(CB);
    quant_v2<<<M_TOTAL, 256>>>(x);
    dim3 grid(N_TOTAL / 128, M_TOTAL / 128);   // 32 x 64 = 2048 CTAs
    gemm_imma<<<grid, 256>>>(SCB, y);
}

// round 12
// speedup vs baseline: 1.3521x; 1.1168x over previous
#include <cuda_runtime.h>
#include <cuda_bf16.h>
#include <cstdint>
#include <math.h>

// Fixed problem sizes
#define M_TOTAL 8192      // B*S = 4*2048
#define N_TOTAL 4096      // OUT
#define K_TOTAL 4096      // IN

// ---- device-global scratch (allocation-free) ----
__device__ __align__(16) int8_t g_xq[(size_t)M_TOTAL * K_TOTAL];  // quantized x
__device__ __align__(16) int8_t g_cb[(size_t)N_TOTAL * K_TOTAL];  // normalized int8 weights
__device__ float g_sx[M_TOTAL];                                   // per-row scale absmax/127
__device__ int   g_cb_mode;   // 0=int8 packed, 1=int32, 2=fp32, 3=bf16

// Tile split: 2048 tiles of 128x128. IMMA : dp4a = 1140 : 908 (~0.557, matches
// measured rate ratio 1845:2245). Interleaved by bid%9 so both types co-reside.
#define TILES_TOTAL 2048
#define IMMA_TILES  1140

// ============================================================================
// Helpers (base-ISA only)
// ============================================================================
__device__ __forceinline__ uint32_t smem_u32(const void* p) {
    uint32_t a;
    asm("{ .reg .u64 t; cvta.to.shared.u64 t, %1; cvt.u32.u64 %0, t; }"
        : "=r"(a) : "l"(p));
    return a;
}
__device__ __forceinline__ void sts128(uint32_t addr, int4 v) {
    asm volatile("st.shared.v4.b32 [%0], {%1, %2, %3, %4};"
                 :: "r"(addr), "r"(v.x), "r"(v.y), "r"(v.z), "r"(v.w) : "memory");
}
__device__ __forceinline__ void ldsm_x4(uint32_t* r, uint32_t addr) {
    asm volatile("ldmatrix.sync.aligned.m8n8.x4.shared.b16 {%0,%1,%2,%3}, [%4];"
                 : "=r"(r[0]), "=r"(r[1]), "=r"(r[2]), "=r"(r[3]) : "r"(addr));
}
__device__ __forceinline__ void mma_s8(int* c, const uint32_t* a, const uint32_t* b) {
    asm volatile("mma.sync.aligned.m16n8k32.row.col.s32.s8.s8.s32 "
                 "{%0,%1,%2,%3}, {%4,%5,%6,%7}, {%8,%9}, {%0,%1,%2,%3};"
                 : "+r"(c[0]), "+r"(c[1]), "+r"(c[2]), "+r"(c[3])
                 : "r"(a[0]), "r"(a[1]), "r"(a[2]), "r"(a[3]),
                   "r"(b[0]), "r"(b[1]));
}
__device__ __forceinline__ uint32_t swoff(int row, int k) {
    return (uint32_t)(row * 64 + k) ^ (((((uint32_t)row) >> 1) & 7u) << 4);
}

// ============================================================================
// Kernel 0a: detect CB storage dtype (proven)
// ============================================================================
__global__ void detect_cb_kernel(const void* __restrict__ cb) {
    __shared__ int ok_i32, ok_f32, ok_bf16;
    if (threadIdx.x == 0) { ok_i32 = 1; ok_f32 = 1; ok_bf16 = 1; }
    __syncthreads();
    const int tid = threadIdx.x;
    bool my_i32 = true, my_f32 = true, my_bf16 = true;
#pragma unroll
    for (int t = 0; t < 16; t++) {
        const int idx = tid + t * 256;
        const int vi = ((const int*)cb)[idx];
        if (vi < -127 || vi > 127) my_i32 = false;
        const float vf = ((const float*)cb)[idx];
        if (!(isfinite(vf) && fabsf(vf) <= 127.0f && vf == rintf(vf))) my_f32 = false;
        const unsigned short h = ((const unsigned short*)cb)[idx];
        __nv_bfloat16 bh = *reinterpret_cast<const __nv_bfloat16*>(&h);
        const float vb = __bfloat162float(bh);
        if (!(isfinite(vb) && fabsf(vb) <= 127.0f && vb == rintf(vb))) my_bf16 = false;
    }
    if (!my_i32)  ok_i32 = 0;
    if (!my_f32)  ok_f32 = 0;
    if (!my_bf16) ok_bf16 = 0;
    __syncthreads();
    if (tid == 0) {
        int mode = 0;
        if      (ok_i32)  mode = 1;
        else if (ok_f32)  mode = 2;
        else if (ok_bf16) mode = 3;
        g_cb_mode = mode;
    }
}

// ============================================================================
// Kernel 0b: normalize CB into packed int8 (proven)
// ============================================================================
__global__ __launch_bounds__(256) void convert_cb_kernel(const void* __restrict__ cb) {
    const int mode = g_cb_mode;
    const size_t q = (size_t)blockIdx.x * 256 + threadIdx.x;
    int* dst = reinterpret_cast<int*>(g_cb);
    if (mode == 0) {
        dst[q] = ((const int*)cb)[q];
    } else if (mode == 1) {
        const int4 v = ((const int4*)cb)[q];
        dst[q] = (int)((unsigned)(v.x & 0xff) | ((unsigned)(v.y & 0xff) << 8) |
                       ((unsigned)(v.z & 0xff) << 16) | ((unsigned)(v.w & 0xff) << 24));
    } else if (mode == 2) {
        const float4 v = ((const float4*)cb)[q];
        const int a = __float2int_rn(v.x) & 0xff, b = __float2int_rn(v.y) & 0xff;
        const int c = __float2int_rn(v.z) & 0xff, d = __float2int_rn(v.w) & 0xff;
        dst[q] = a | (b << 8) | (c << 16) | (d << 24);
    } else {
        const __nv_bfloat162* p = reinterpret_cast<const __nv_bfloat162*>(cb);
        const __nv_bfloat162 v0 = p[q * 2], v1 = p[q * 2 + 1];
        const int a = __float2int_rn(__bfloat162float(v0.x)) & 0xff;
        const int b = __float2int_rn(__bfloat162float(v0.y)) & 0xff;
        const int c = __float2int_rn(__bfloat162float(v1.x)) & 0xff;
        const int d = __float2int_rn(__bfloat162float(v1.y)) & 0xff;
        dst[q] = a | (b << 8) | (c << 16) | (d << 24);
    }
}

// ============================================================================
// Kernel 1: per-row dynamic int8 quantization of x (proven)
// ============================================================================
__global__ __launch_bounds__(256) void quant_v2(const float* __restrict__ x) {
    __shared__ float smax[256];
    const int row = blockIdx.x;
    const int tid = threadIdx.x;
    const float* xr = x + (size_t)row * K_TOTAL;
    float v[16];
    float am = 0.0f;
#pragma unroll
    for (int t = 0; t < 16; t++) {
        v[t] = xr[tid + t * 256];
        am = fmaxf(am, fabsf(v[t]));
    }
    smax[tid] = am;
    __syncthreads();
#pragma unroll
    for (int off = 128; off > 0; off >>= 1) {
        if (tid < off) smax[tid] = fmaxf(smax[tid], smax[tid + off]);
        __syncthreads();
    }
    const float s = smax[0] / 127.0f;
    int8_t* q = g_xq + (size_t)row * K_TOTAL;
#pragma unroll
    for (int t = 0; t < 16; t++) q[tid + t * 256] = (int8_t)__float2int_rn(v[t] / s);
    if (tid == 0) g_sx[row] = s;
}

// ============================================================================
// Kernel 2: HYBRID GEMM. Each CTA computes one 128x128 tile using either
//   (a) the legacy-tensor IMMA engine (R11, tensor pipe), or
//   (b) the dp4a engine (R8, fma/alu pipe),
// type-interleaved by bid%9 so both engines co-reside per SM and the two
// execution pipes overlap. 32KB static SMEM union; __launch_bounds__(256,2)
// keeps 2 CTAs/SM.
// ============================================================================
#define BK 64
#define KW 16

__global__ __launch_bounds__(256, 2) void gemm_hybrid(const float* __restrict__ SCB,
                                                      float* __restrict__ y) {
    __shared__ __align__(16) int8_t smem_raw[4 * 128 * BK];   // 32 KB union

    const int tid = threadIdx.x;
    const int bid = blockIdx.x;
    const int r9 = bid % 9, q9 = bid / 9;
    const bool isImma = (r9 < 5);
    const int tile = isImma ? (q9 * 5 + r9) : (IMMA_TILES + q9 * 4 + (r9 - 5));
    const int bm = tile >> 5;       // 0..63
    const int bn = tile & 31;       // 0..31

    if (isImma) {
        // ================= IMMA engine (verbatim R11 core) =================
        int8_t (*As)[128 * BK] = reinterpret_cast<int8_t(*)[128 * BK]>(smem_raw);
        int8_t (*Bs)[128 * BK] = reinterpret_cast<int8_t(*)[128 * BK]>(smem_raw + 2 * 128 * BK);

        const int wid = tid >> 5, lane = tid & 31;
        const int wm = wid >> 2, wn = wid & 3;

        const int pr0 = tid >> 2, pseg = tid & 3, pr1 = pr0 + 64;
        const int8_t* aG0 = g_xq + (size_t)(bm * 128 + pr0) * K_TOTAL + pseg * 16;
        const int8_t* aG1 = g_xq + (size_t)(bm * 128 + pr1) * K_TOTAL + pseg * 16;
        const int8_t* bG0 = g_cb + (size_t)(bn * 128 + pr0) * K_TOTAL + pseg * 16;
        const int8_t* bG1 = g_cb + (size_t)(bn * 128 + pr1) * K_TOTAL + pseg * 16;
        const uint32_t so0 = swoff(pr0, pseg * 16);
        const uint32_t so1 = swoff(pr1, pseg * 16);

        const uint32_t aSm = smem_u32(&As[0][0]);
        const uint32_t bSm = smem_u32(&Bs[0][0]);

        const int q = lane >> 3, lr = lane & 7;
        const int aRowL = wm * 64 + (q & 1) * 8 + lr;
        const int aKL   = (q >> 1) * 16;
        const int bRowL = wn * 32 + (q >> 1) * 8 + lr;
        const int bKL   = (q & 1) * 16;

        int acc[16][4];
#pragma unroll
        for (int f = 0; f < 16; f++)
#pragma unroll
            for (int r = 0; r < 4; r++) acc[f][r] = 0;

        int4 ra0 = *reinterpret_cast<const int4*>(aG0);
        int4 ra1 = *reinterpret_cast<const int4*>(aG1);
        int4 rb0 = *reinterpret_cast<const int4*>(bG0);
        int4 rb1 = *reinterpret_cast<const int4*>(bG1);
        sts128(aSm + so0, ra0); sts128(aSm + so1, ra1);
        sts128(bSm + so0, rb0); sts128(bSm + so1, rb1);
        __syncthreads();

        const int NT = K_TOTAL / BK;
        for (int kt = 0; kt < NT; kt++) {
            const int buf = kt & 1;
            if (kt + 1 < NT) {
                ra0 = *reinterpret_cast<const int4*>(aG0 + (kt + 1) * BK);
                ra1 = *reinterpret_cast<const int4*>(aG1 + (kt + 1) * BK);
                rb0 = *reinterpret_cast<const int4*>(bG0 + (kt + 1) * BK);
                rb1 = *reinterpret_cast<const int4*>(bG1 + (kt + 1) * BK);
            }
            const uint32_t aB = aSm + buf * (128 * BK);
            const uint32_t bB = bSm + buf * (128 * BK);

#pragma unroll
            for (int ks = 0; ks < 2; ks++) {
                uint32_t a[4][4], b[4][2];
#pragma unroll
                for (int fi = 0; fi < 4; fi++)
                    ldsm_x4(a[fi], aB + swoff(aRowL + fi * 16, aKL + ks * 32));
#pragma unroll
                for (int pr = 0; pr < 2; pr++) {
                    uint32_t t4[4];
                    ldsm_x4(t4, bB + swoff(bRowL + pr * 16, bKL + ks * 32));
                    b[pr * 2][0] = t4[0]; b[pr * 2][1] = t4[1];
                    b[pr * 2 + 1][0] = t4[2]; b[pr * 2 + 1][1] = t4[3];
                }
#pragma unroll
                for (int fi = 0; fi < 4; fi++)
#pragma unroll
                    for (int fj = 0; fj < 4; fj++)
                        mma_s8(acc[fi * 4 + fj], a[fi], b[fj]);
            }

            __syncthreads();
            if (kt + 1 < NT) {
                const uint32_t aN = aSm + (buf ^ 1) * (128 * BK);
                const uint32_t bN = bSm + (buf ^ 1) * (128 * BK);
                sts128(aN + so0, ra0); sts128(aN + so1, ra1);
                sts128(bN + so0, rb0); sts128(bN + so1, rb1);
            }
            __syncthreads();
        }

        const int g = lane >> 2, tg = lane & 3;
        float scb[8];
#pragma unroll
        for (int fj = 0; fj < 4; fj++) {
            const int n = bn * 128 + wn * 32 + fj * 8 + tg * 2;
            scb[fj * 2]     = SCB[n]     * (1.0f / 127.0f);
            scb[fj * 2 + 1] = SCB[n + 1] * (1.0f / 127.0f);
        }
#pragma unroll
        for (int fi = 0; fi < 4; fi++) {
#pragma unroll
            for (int h = 0; h < 2; h++) {
                const int m = bm * 128 + wm * 64 + fi * 16 + g + h * 8;
                const float sm = g_sx[m];
                float* yr = y + (size_t)m * N_TOTAL + bn * 128 + wn * 32;
#pragma unroll
                for (int fj = 0; fj < 4; fj++) {
                    const int* c = acc[fi * 4 + fj];
                    float2 o;
                    o.x = (float)c[h * 2]     * sm * scb[fj * 2];
                    o.y = (float)c[h * 2 + 1] * sm * scb[fj * 2 + 1];
                    *reinterpret_cast<float2*>(yr + fj * 8 + tg * 2) = o;
                }
            }
        }
    } else {
        // ================= dp4a engine (verbatim R8 core) =================
        int* AsI = reinterpret_cast<int*>(smem_raw);                     // [128*KW]
        int* BsI = reinterpret_cast<int*>(smem_raw) + 128 * KW;          // [128*KW]

        const int r0 = tid >> 2, s0 = tid & 3, r1 = r0 + 64;
        const int8_t* aP0 = g_xq + (size_t)(bm * 128 + r0) * K_TOTAL + s0 * 16;
        const int8_t* aP1 = g_xq + (size_t)(bm * 128 + r1) * K_TOTAL + s0 * 16;
        const int8_t* bP0 = g_cb + (size_t)(bn * 128 + r0) * K_TOTAL + s0 * 16;
        const int8_t* bP1 = g_cb + (size_t)(bn * 128 + r1) * K_TOTAL + s0 * 16;

        int acc[8][8];
#pragma unroll
        for (int i = 0; i < 8; i++)
#pragma unroll
            for (int j = 0; j < 8; j++) acc[i][j] = 0;

        const int ty = tid >> 4, tx = tid & 15;
        const int sw0 = r0 >> 3, sw1 = r1 >> 3;

        for (int kt = 0; kt < K_TOTAL / 64; kt++) {
            const int4 a0 = *reinterpret_cast<const int4*>(aP0 + kt * 64);
            const int4 a1 = *reinterpret_cast<const int4*>(aP1 + kt * 64);
            const int4 b0 = *reinterpret_cast<const int4*>(bP0 + kt * 64);
            const int4 b1 = *reinterpret_cast<const int4*>(bP1 + kt * 64);

            __syncthreads();

            AsI[r0 * KW + ((s0 * 4 + 0) ^ sw0)] = a0.x;
            AsI[r0 * KW + ((s0 * 4 + 1) ^ sw0)] = a0.y;
            AsI[r0 * KW + ((s0 * 4 + 2) ^ sw0)] = a0.z;
            AsI[r0 * KW + ((s0 * 4 + 3) ^ sw0)] = a0.w;
            AsI[r1 * KW + ((s0 * 4 + 0) ^ sw1)] = a1.x;
            AsI[r1 * KW + ((s0 * 4 + 1) ^ sw1)] = a1.y;
            AsI[r1 * KW + ((s0 * 4 + 2) ^ sw1)] = a1.z;
            AsI[r1 * KW + ((s0 * 4 + 3) ^ sw1)] = a1.w;
            BsI[r0 * KW + ((s0 * 4 + 0) ^ sw0)] = b0.x;
            BsI[r0 * KW + ((s0 * 4 + 1) ^ sw0)] = b0.y;
            BsI[r0 * KW + ((s0 * 4 + 2) ^ sw0)] = b0.z;
            BsI[r0 * KW + ((s0 * 4 + 3) ^ sw0)] = b0.w;
            BsI[r1 * KW + ((s0 * 4 + 0) ^ sw1)] = b1.x;
            BsI[r1 * KW + ((s0 * 4 + 1) ^ sw1)] = b1.y;
            BsI[r1 * KW + ((s0 * 4 + 2) ^ sw1)] = b1.z;
            BsI[r1 * KW + ((s0 * 4 + 3) ^ sw1)] = b1.w;

            __syncthreads();

#pragma unroll
            for (int kw = 0; kw < KW; kw++) {
                int a[8], b[8];
#pragma unroll
                for (int i = 0; i < 8; i++)
                    a[i] = AsI[(ty * 8 + i) * KW + (kw ^ ty)];
#pragma unroll
                for (int j = 0; j < 8; j++)
                    b[j] = BsI[(tx * 8 + j) * KW + (kw ^ tx)];
#pragma unroll
                for (int i = 0; i < 8; i++)
#pragma unroll
                    for (int j = 0; j < 8; j++)
                        acc[i][j] = __dp4a(a[i], b[j], acc[i][j]);
            }
        }

        const int m0 = bm * 128 + ty * 8;
        const int n0 = bn * 128 + tx * 8;
#pragma unroll
        for (int i = 0; i < 8; i++) {
            const float sm = g_sx[m0 + i];
            float* yr = y + (size_t)(m0 + i) * N_TOTAL;
#pragma unroll
            for (int j = 0; j < 8; j++) {
                yr[n0 + j] = ((float)acc[i][j] * sm) * (SCB[n0 + j] * (1.0f / 127.0f));
            }
        }
    }
}

// ============================================================================
// Launch. Inputs bound by element count:
//   x: 33,554,432   CB: 16,777,216 (dtype auto-detected)   SCB: 4,096
// ============================================================================
extern "C" void kernel_launch(void* const* d_in, const int* in_sizes, int n_in,
                              void* d_out, int out_size) {
    const float* x   = nullptr;
    const void*  CB  = nullptr;
    const float* SCB = nullptr;
    for (int i = 0; i < n_in; i++) {
        if (in_sizes[i] == 33554432)      x   = (const float*)d_in[i];
        else if (in_sizes[i] == 16777216) CB  = d_in[i];
        else if (in_sizes[i] == 4096)     SCB = (const float*)d_in[i];
    }
    float* y = (float*)d_out;

    detect_cb_kernel<<<1, 256>>>(CB);
    convert_cb_kernel<<<(N_TOTAL * K_TOTAL / 4) / 256, 256>>>(CB);
    quant_v2<<<M_TOTAL, 256>>>(x);
    gemm_hybrid<<<TILES_TOTAL, 256>>>(SCB, y);
}

// round 13
// speedup vs baseline: 1.5670x; 1.1589x over previous
#include <cuda_runtime.h>
#include <cuda_bf16.h>
#include <cstdint>
#include <math.h>

// Fixed problem sizes
#define M_TOTAL 8192      // B*S = 4*2048
#define N_TOTAL 4096      // OUT
#define K_TOTAL 4096      // IN

// ---- device-global scratch (allocation-free) ----
__device__ __align__(16) int8_t g_xq[(size_t)M_TOTAL * K_TOTAL];  // quantized x
__device__ __align__(16) int8_t g_cb[(size_t)N_TOTAL * K_TOTAL];  // normalized int8 weights
__device__ float g_sx[M_TOTAL];                                   // per-row scale absmax/127
__device__ int   g_cb_mode;   // 0=int8 packed, 1=int32, 2=fp32, 3=bf16

// ============================================================================
// Helpers (base-ISA only)
// ============================================================================
__device__ __forceinline__ uint32_t smem_u32(const void* p) {
    uint32_t a;
    asm("{ .reg .u64 t; cvta.to.shared.u64 t, %1; cvt.u32.u64 %0, t; }"
        : "=r"(a) : "l"(p));
    return a;
}
__device__ __forceinline__ void sts128(uint32_t addr, int4 v) {
    asm volatile("st.shared.v4.b32 [%0], {%1, %2, %3, %4};"
                 :: "r"(addr), "r"(v.x), "r"(v.y), "r"(v.z), "r"(v.w) : "memory");
}
__device__ __forceinline__ void ldsm_x4(uint32_t* r, uint32_t addr) {
    asm volatile("ldmatrix.sync.aligned.m8n8.x4.shared.b16 {%0,%1,%2,%3}, [%4];"
                 : "=r"(r[0]), "=r"(r[1]), "=r"(r[2]), "=r"(r[3]) : "r"(addr));
}
__device__ __forceinline__ void mma_s8(int* c, const uint32_t* a, const uint32_t* b) {
    asm volatile("mma.sync.aligned.m16n8k32.row.col.s32.s8.s8.s32 "
                 "{%0,%1,%2,%3}, {%4,%5,%6,%7}, {%8,%9}, {%0,%1,%2,%3};"
                 : "+r"(c[0]), "+r"(c[1]), "+r"(c[2]), "+r"(c[3])
                 : "r"(a[0]), "r"(a[1]), "r"(a[2]), "r"(a[3]),
                   "r"(b[0]), "r"(b[1]));
}
// named barrier (independent sync domains for the two engine halves)
__device__ __forceinline__ void barx(int id, int cnt) {
    asm volatile("bar.sync %0, %1;" :: "r"(id), "r"(cnt) : "memory");
}
// swizzled byte offset for [rows x 64B] tiles (proven in R11)
__device__ __forceinline__ uint32_t swoff(int row, int k) {
    return (uint32_t)(row * 64 + k) ^ (((((uint32_t)row) >> 1) & 7u) << 4);
}

// ============================================================================
// Kernel 0a: detect CB storage dtype (proven)
// ============================================================================
__global__ void detect_cb_kernel(const void* __restrict__ cb) {
    __shared__ int ok_i32, ok_f32, ok_bf16;
    if (threadIdx.x == 0) { ok_i32 = 1; ok_f32 = 1; ok_bf16 = 1; }
    __syncthreads();
    const int tid = threadIdx.x;
    bool my_i32 = true, my_f32 = true, my_bf16 = true;
#pragma unroll
    for (int t = 0; t < 16; t++) {
        const int idx = tid + t * 256;
        const int vi = ((const int*)cb)[idx];
        if (vi < -127 || vi > 127) my_i32 = false;
        const float vf = ((const float*)cb)[idx];
        if (!(isfinite(vf) && fabsf(vf) <= 127.0f && vf == rintf(vf))) my_f32 = false;
        const unsigned short h = ((const unsigned short*)cb)[idx];
        __nv_bfloat16 bh = *reinterpret_cast<const __nv_bfloat16*>(&h);
        const float vb = __bfloat162float(bh);
        if (!(isfinite(vb) && fabsf(vb) <= 127.0f && vb == rintf(vb))) my_bf16 = false;
    }
    if (!my_i32)  ok_i32 = 0;
    if (!my_f32)  ok_f32 = 0;
    if (!my_bf16) ok_bf16 = 0;
    __syncthreads();
    if (tid == 0) {
        int mode = 0;
        if      (ok_i32)  mode = 1;
        else if (ok_f32)  mode = 2;
        else if (ok_bf16) mode = 3;
        g_cb_mode = mode;
    }
}

// ============================================================================
// Kernel 0b: normalize CB into packed int8 (proven)
// ============================================================================
__global__ __launch_bounds__(256) void convert_cb_kernel(const void* __restrict__ cb) {
    const int mode = g_cb_mode;
    const size_t q = (size_t)blockIdx.x * 256 + threadIdx.x;
    int* dst = reinterpret_cast<int*>(g_cb);
    if (mode == 0) {
        dst[q] = ((const int*)cb)[q];
    } else if (mode == 1) {
        const int4 v = ((const int4*)cb)[q];
        dst[q] = (int)((unsigned)(v.x & 0xff) | ((unsigned)(v.y & 0xff) << 8) |
                       ((unsigned)(v.z & 0xff) << 16) | ((unsigned)(v.w & 0xff) << 24));
    } else if (mode == 2) {
        const float4 v = ((const float4*)cb)[q];
        const int a = __float2int_rn(v.x) & 0xff, b = __float2int_rn(v.y) & 0xff;
        const int c = __float2int_rn(v.z) & 0xff, d = __float2int_rn(v.w) & 0xff;
        dst[q] = a | (b << 8) | (c << 16) | (d << 24);
    } else {
        const __nv_bfloat162* p = reinterpret_cast<const __nv_bfloat162*>(cb);
        const __nv_bfloat162 v0 = p[q * 2], v1 = p[q * 2 + 1];
        const int a = __float2int_rn(__bfloat162float(v0.x)) & 0xff;
        const int b = __float2int_rn(__bfloat162float(v0.y)) & 0xff;
        const int c = __float2int_rn(__bfloat162float(v1.x)) & 0xff;
        const int d = __float2int_rn(__bfloat162float(v1.y)) & 0xff;
        dst[q] = a | (b << 8) | (c << 16) | (d << 24);
    }
}

// ============================================================================
// Kernel 1: per-row dynamic int8 quantization of x (proven)
// ============================================================================
__global__ __launch_bounds__(256) void quant_v2(const float* __restrict__ x) {
    __shared__ float smax[256];
    const int row = blockIdx.x;
    const int tid = threadIdx.x;
    const float* xr = x + (size_t)row * K_TOTAL;
    float v[16];
    float am = 0.0f;
#pragma unroll
    for (int t = 0; t < 16; t++) {
        v[t] = xr[tid + t * 256];
        am = fmaxf(am, fabsf(v[t]));
    }
    smax[tid] = am;
    __syncthreads();
#pragma unroll
    for (int off = 128; off > 0; off >>= 1) {
        if (tid < off) smax[tid] = fmaxf(smax[tid], smax[tid + off]);
        __syncthreads();
    }
    const float s = smax[0] / 127.0f;
    int8_t* q = g_xq + (size_t)row * K_TOTAL;
#pragma unroll
    for (int t = 0; t < 16; t++) q[tid + t * 256] = (int8_t)__float2int_rn(v[t] / s);
    if (tid == 0) g_sx[row] = s;
}

// ============================================================================
// Kernel 2: INTRA-CTA HYBRID GEMM. Each CTA computes one 128x128 tile:
//   warps 0-3 : IMMA engine (tensor pipe) on columns n 0..63   (2x2 x 64x32)
//   warps 4-7 : dp4a engine (fma pipe)    on columns n 64..127 (128 thr, 8x8)
// The halves sync on independent named barriers (1 and 2) with disjoint SMEM,
// so every CTA — hence every SM — drives both execution pipes concurrently.
// ============================================================================
#define BK 64
#define KW 16

__global__ __launch_bounds__(256, 2) void gemm_hybrid2(const float* __restrict__ SCB,
                                                       float* __restrict__ y) {
    __shared__ __align__(16) int8_t sIA[2][128 * BK];   // IMMA A: 2 x 8 KB
    __shared__ __align__(16) int8_t sIB[2][64 * BK];    // IMMA B: 2 x 4 KB
    __shared__ __align__(16) int    sDA[128 * KW];      // dp4a A: 8 KB
    __shared__ __align__(16) int    sDB[64 * KW];       // dp4a B: 4 KB

    const int tid = threadIdx.x;
    const int bn = blockIdx.x;     // 0..31
    const int bm = blockIdx.y;     // 0..63

    if (tid < 128) {
        // ==================== IMMA half: n 0..63 ====================
        const int wid = tid >> 5;          // 0..3
        const int lane = tid & 31;
        const int wm = wid >> 1;           // 0..1 -> m offset wm*64
        const int wn2 = wid & 1;           // 0..1 -> n offset wn2*32

        // producer: A 512 chunks (4/thr), B 256 chunks (2/thr)
        const int8_t* aG[4]; uint32_t aSo[4];
#pragma unroll
        for (int i = 0; i < 4; i++) {
            const int c = tid + i * 128;
            const int r = c >> 2, s = c & 3;
            aG[i] = g_xq + (size_t)(bm * 128 + r) * K_TOTAL + s * 16;
            aSo[i] = swoff(r, s * 16);
        }
        const int8_t* bG[2]; uint32_t bSo[2];
#pragma unroll
        for (int i = 0; i < 2; i++) {
            const int c = tid + i * 128;
            const int r = c >> 2, s = c & 3;        // r: 0..63 (n rows 0..63)
            bG[i] = g_cb + (size_t)(bn * 128 + r) * K_TOTAL + s * 16;
            bSo[i] = swoff(r, s * 16);
        }

        const uint32_t aSm = smem_u32(&sIA[0][0]);
        const uint32_t bSm = smem_u32(&sIB[0][0]);

        const int q = lane >> 3, lr = lane & 7;
        const int aRowL = wm * 64 + (q & 1) * 8 + lr;
        const int aKL   = (q >> 1) * 16;
        const int bRowL = wn2 * 32 + (q >> 1) * 8 + lr;
        const int bKL   = (q & 1) * 16;

        int acc[16][4];
#pragma unroll
        for (int f = 0; f < 16; f++)
#pragma unroll
            for (int r = 0; r < 4; r++) acc[f][r] = 0;

        int4 ra[4], rb[2];
#pragma unroll
        for (int i = 0; i < 4; i++) ra[i] = *reinterpret_cast<const int4*>(aG[i]);
#pragma unroll
        for (int i = 0; i < 2; i++) rb[i] = *reinterpret_cast<const int4*>(bG[i]);
#pragma unroll
        for (int i = 0; i < 4; i++) sts128(aSm + aSo[i], ra[i]);
#pragma unroll
        for (int i = 0; i < 2; i++) sts128(bSm + bSo[i], rb[i]);
        barx(1, 128);

        const int NT = K_TOTAL / BK;   // 64
        for (int kt = 0; kt < NT; kt++) {
            const int buf = kt & 1;
            if (kt + 1 < NT) {
#pragma unroll
                for (int i = 0; i < 4; i++)
                    ra[i] = *reinterpret_cast<const int4*>(aG[i] + (kt + 1) * BK);
#pragma unroll
                for (int i = 0; i < 2; i++)
                    rb[i] = *reinterpret_cast<const int4*>(bG[i] + (kt + 1) * BK);
            }
            const uint32_t aB = aSm + buf * (128 * BK);
            const uint32_t bB = bSm + buf * (64 * BK);

#pragma unroll
            for (int ks = 0; ks < 2; ks++) {
                uint32_t a[4][4], b[4][2];
#pragma unroll
                for (int fi = 0; fi < 4; fi++)
                    ldsm_x4(a[fi], aB + swoff(aRowL + fi * 16, aKL + ks * 32));
#pragma unroll
                for (int pr = 0; pr < 2; pr++) {
                    uint32_t t4[4];
                    ldsm_x4(t4, bB + swoff(bRowL + pr * 16, bKL + ks * 32));
                    b[pr * 2][0] = t4[0]; b[pr * 2][1] = t4[1];
                    b[pr * 2 + 1][0] = t4[2]; b[pr * 2 + 1][1] = t4[3];
                }
#pragma unroll
                for (int fi = 0; fi < 4; fi++)
#pragma unroll
                    for (int fj = 0; fj < 4; fj++)
                        mma_s8(acc[fi * 4 + fj], a[fi], b[fj]);
            }

            barx(1, 128);
            if (kt + 1 < NT) {
                const uint32_t aN = aSm + (buf ^ 1) * (128 * BK);
                const uint32_t bN = bSm + (buf ^ 1) * (64 * BK);
#pragma unroll
                for (int i = 0; i < 4; i++) sts128(aN + aSo[i], ra[i]);
#pragma unroll
                for (int i = 0; i < 2; i++) sts128(bN + bSo[i], rb[i]);
            }
            barx(1, 128);
        }

        // epilogue
        const int g = lane >> 2, tg = lane & 3;
        float scb[8];
#pragma unroll
        for (int fj = 0; fj < 4; fj++) {
            const int n = bn * 128 + wn2 * 32 + fj * 8 + tg * 2;
            scb[fj * 2]     = SCB[n]     * (1.0f / 127.0f);
            scb[fj * 2 + 1] = SCB[n + 1] * (1.0f / 127.0f);
        }
#pragma unroll
        for (int fi = 0; fi < 4; fi++) {
#pragma unroll
            for (int h = 0; h < 2; h++) {
                const int m = bm * 128 + wm * 64 + fi * 16 + g + h * 8;
                const float sm = g_sx[m];
                float* yr = y + (size_t)m * N_TOTAL + bn * 128 + wn2 * 32;
#pragma unroll
                for (int fj = 0; fj < 4; fj++) {
                    const int* c = acc[fi * 4 + fj];
                    float2 o;
                    o.x = (float)c[h * 2]     * sm * scb[fj * 2];
                    o.y = (float)c[h * 2 + 1] * sm * scb[fj * 2 + 1];
                    *reinterpret_cast<float2*>(yr + fj * 8 + tg * 2) = o;
                }
            }
        }
    } else {
        // ==================== dp4a half: n 64..127 ====================
        const int t = tid - 128;           // 0..127

        // producer: A 512 chunks (4/thr), B 256 chunks (2/thr)
        const int8_t* aP[4]; int aRow[4], aSeg[4];
#pragma unroll
        for (int i = 0; i < 4; i++) {
            const int c = t + i * 128;
            aRow[i] = c >> 2; aSeg[i] = c & 3;
            aP[i] = g_xq + (size_t)(bm * 128 + aRow[i]) * K_TOTAL + aSeg[i] * 16;
        }
        const int8_t* bP[2]; int bRow[2], bSeg[2];
#pragma unroll
        for (int i = 0; i < 2; i++) {
            const int c = t + i * 128;
            bRow[i] = c >> 2; bSeg[i] = c & 3;      // local n rows 0..63
            bP[i] = g_cb + (size_t)(bn * 128 + 64 + bRow[i]) * K_TOTAL + bSeg[i] * 16;
        }

        int acc[8][8];
#pragma unroll
        for (int i = 0; i < 8; i++)
#pragma unroll
            for (int j = 0; j < 8; j++) acc[i][j] = 0;

        const int ty = t >> 3;    // 0..15 -> rows ty*8..+7
        const int tx = t & 7;     // 0..7  -> local cols tx*8..+7

        for (int kt = 0; kt < K_TOTAL / 64; kt++) {
            int4 av[4], bv[2];
#pragma unroll
            for (int i = 0; i < 4; i++)
                av[i] = *reinterpret_cast<const int4*>(aP[i] + kt * 64);
#pragma unroll
            for (int i = 0; i < 2; i++)
                bv[i] = *reinterpret_cast<const int4*>(bP[i] + kt * 64);

            barx(2, 128);   // previous tile's reads complete

#pragma unroll
            for (int i = 0; i < 4; i++) {
                const int r = aRow[i], sw = r >> 3;
                sDA[r * KW + ((aSeg[i] * 4 + 0) ^ sw)] = av[i].x;
                sDA[r * KW + ((aSeg[i] * 4 + 1) ^ sw)] = av[i].y;
                sDA[r * KW + ((aSeg[i] * 4 + 2) ^ sw)] = av[i].z;
                sDA[r * KW + ((aSeg[i] * 4 + 3) ^ sw)] = av[i].w;
            }
#pragma unroll
            for (int i = 0; i < 2; i++) {
                const int r = bRow[i], sw = r >> 3;
                sDB[r * KW + ((bSeg[i] * 4 + 0) ^ sw)] = bv[i].x;
                sDB[r * KW + ((bSeg[i] * 4 + 1) ^ sw)] = bv[i].y;
                sDB[r * KW + ((bSeg[i] * 4 + 2) ^ sw)] = bv[i].z;
                sDB[r * KW + ((bSeg[i] * 4 + 3) ^ sw)] = bv[i].w;
            }

            barx(2, 128);

#pragma unroll
            for (int kw = 0; kw < KW; kw++) {
                int a[8], b[8];
#pragma unroll
                for (int i = 0; i < 8; i++)
                    a[i] = sDA[(ty * 8 + i) * KW + (kw ^ ty)];
#pragma unroll
                for (int j = 0; j < 8; j++)
                    b[j] = sDB[(tx * 8 + j) * KW + (kw ^ tx)];
#pragma unroll
                for (int i = 0; i < 8; i++)
#pragma unroll
                    for (int j = 0; j < 8; j++)
                        acc[i][j] = __dp4a(a[i], b[j], acc[i][j]);
            }
        }

        // epilogue
        const int m0 = bm * 128 + ty * 8;
        const int n0 = bn * 128 + 64 + tx * 8;
#pragma unroll
        for (int i = 0; i < 8; i++) {
            const float sm = g_sx[m0 + i];
            float* yr = y + (size_t)(m0 + i) * N_TOTAL;
#pragma unroll
            for (int j = 0; j < 8; j++) {
                yr[n0 + j] = ((float)acc[i][j] * sm) * (SCB[n0 + j] * (1.0f / 127.0f));
            }
        }
    }
}

// ============================================================================
// Launch. Inputs bound by element count:
//   x: 33,554,432   CB: 16,777,216 (dtype auto-detected)   SCB: 4,096
// ============================================================================
extern "C" void kernel_launch(void* const* d_in, const int* in_sizes, int n_in,
                              void* d_out, int out_size) {
    const float* x   = nullptr;
    const void*  CB  = nullptr;
    const float* SCB = nullptr;
    for (int i = 0; i < n_in; i++) {
        if (in_sizes[i] == 33554432)      x   = (const float*)d_in[i];
        else if (in_sizes[i] == 16777216) CB  = d_in[i];
        else if (in_sizes[i] == 4096)     SCB = (const float*)d_in[i];
    }
    float* y = (float*)d_out;

    detect_cb_kernel<<<1, 256>>>(CB);
    convert_cb_kernel<<<(N_TOTAL * K_TOTAL / 4) / 256, 256>>>(CB);
    quant_v2<<<M_TOTAL, 256>>>(x);
    dim3 grid(N_TOTAL / 128, M_TOTAL / 128);   // 32 x 64 = 2048 CTAs
    gemm_hybrid2<<<grid, 256>>>(SCB, y);
}

// round 14
// speedup vs baseline: 1.6700x; 1.0657x over previous
#include <cuda_runtime.h>
#include <cuda_bf16.h>
#include <cstdint>
#include <math.h>

// Fixed problem sizes
#define M_TOTAL 8192      // B*S = 4*2048
#define N_TOTAL 4096      // OUT
#define K_TOTAL 4096      // IN

// ---- device-global scratch (allocation-free) ----
__device__ __align__(16) int8_t g_xq[(size_t)M_TOTAL * K_TOTAL];  // quantized x
__device__ __align__(16) int8_t g_cb[(size_t)N_TOTAL * K_TOTAL];  // normalized int8 weights
__device__ float g_sx[M_TOTAL];                                   // per-row scale absmax/127
__device__ int   g_cb_mode;   // 0=int8 packed, 1=int32, 2=fp32, 3=bf16

// ============================================================================
// Helpers (base-ISA only)
// ============================================================================
__device__ __forceinline__ uint32_t smem_u32(const void* p) {
    uint32_t a;
    asm("{ .reg .u64 t; cvta.to.shared.u64 t, %1; cvt.u32.u64 %0, t; }"
        : "=r"(a) : "l"(p));
    return a;
}
__device__ __forceinline__ void sts128(uint32_t addr, int4 v) {
    asm volatile("st.shared.v4.b32 [%0], {%1, %2, %3, %4};"
                 :: "r"(addr), "r"(v.x), "r"(v.y), "r"(v.z), "r"(v.w) : "memory");
}
__device__ __forceinline__ void ldsm_x4(uint32_t* r, uint32_t addr) {
    asm volatile("ldmatrix.sync.aligned.m8n8.x4.shared.b16 {%0,%1,%2,%3}, [%4];"
                 : "=r"(r[0]), "=r"(r[1]), "=r"(r[2]), "=r"(r[3]) : "r"(addr));
}
__device__ __forceinline__ void mma_s8(int* c, const uint32_t* a, const uint32_t* b) {
    asm volatile("mma.sync.aligned.m16n8k32.row.col.s32.s8.s8.s32 "
                 "{%0,%1,%2,%3}, {%4,%5,%6,%7}, {%8,%9}, {%0,%1,%2,%3};"
                 : "+r"(c[0]), "+r"(c[1]), "+r"(c[2]), "+r"(c[3])
                 : "r"(a[0]), "r"(a[1]), "r"(a[2]), "r"(a[3]),
                   "r"(b[0]), "r"(b[1]));
}
// named barrier (independent sync domains for the two engine halves)
__device__ __forceinline__ void barx(int id, int cnt) {
    asm volatile("bar.sync %0, %1;" :: "r"(id), "r"(cnt) : "memory");
}
// swizzled byte offset for [rows x 64B] tiles (proven in R11)
__device__ __forceinline__ uint32_t swoff(int row, int k) {
    return (uint32_t)(row * 64 + k) ^ (((((uint32_t)row) >> 1) & 7u) << 4);
}

// ============================================================================
// Kernel 0a: detect CB storage dtype (proven)
// ============================================================================
__global__ void detect_cb_kernel(const void* __restrict__ cb) {
    __shared__ int ok_i32, ok_f32, ok_bf16;
    if (threadIdx.x == 0) { ok_i32 = 1; ok_f32 = 1; ok_bf16 = 1; }
    __syncthreads();
    const int tid = threadIdx.x;
    bool my_i32 = true, my_f32 = true, my_bf16 = true;
#pragma unroll
    for (int t = 0; t < 16; t++) {
        const int idx = tid + t * 256;
        const int vi = ((const int*)cb)[idx];
        if (vi < -127 || vi > 127) my_i32 = false;
        const float vf = ((const float*)cb)[idx];
        if (!(isfinite(vf) && fabsf(vf) <= 127.0f && vf == rintf(vf))) my_f32 = false;
        const unsigned short h = ((const unsigned short*)cb)[idx];
        __nv_bfloat16 bh = *reinterpret_cast<const __nv_bfloat16*>(&h);
        const float vb = __bfloat162float(bh);
        if (!(isfinite(vb) && fabsf(vb) <= 127.0f && vb == rintf(vb))) my_bf16 = false;
    }
    if (!my_i32)  ok_i32 = 0;
    if (!my_f32)  ok_f32 = 0;
    if (!my_bf16) ok_bf16 = 0;
    __syncthreads();
    if (tid == 0) {
        int mode = 0;
        if      (ok_i32)  mode = 1;
        else if (ok_f32)  mode = 2;
        else if (ok_bf16) mode = 3;
        g_cb_mode = mode;
    }
}

// ============================================================================
// Kernel 0b: normalize CB into packed int8 (proven)
// ============================================================================
__global__ __launch_bounds__(256) void convert_cb_kernel(const void* __restrict__ cb) {
    const int mode = g_cb_mode;
    const size_t q = (size_t)blockIdx.x * 256 + threadIdx.x;
    int* dst = reinterpret_cast<int*>(g_cb);
    if (mode == 0) {
        dst[q] = ((const int*)cb)[q];
    } else if (mode == 1) {
        const int4 v = ((const int4*)cb)[q];
        dst[q] = (int)((unsigned)(v.x & 0xff) | ((unsigned)(v.y & 0xff) << 8) |
                       ((unsigned)(v.z & 0xff) << 16) | ((unsigned)(v.w & 0xff) << 24));
    } else if (mode == 2) {
        const float4 v = ((const float4*)cb)[q];
        const int a = __float2int_rn(v.x) & 0xff, b = __float2int_rn(v.y) & 0xff;
        const int c = __float2int_rn(v.z) & 0xff, d = __float2int_rn(v.w) & 0xff;
        dst[q] = a | (b << 8) | (c << 16) | (d << 24);
    } else {
        const __nv_bfloat162* p = reinterpret_cast<const __nv_bfloat162*>(cb);
        const __nv_bfloat162 v0 = p[q * 2], v1 = p[q * 2 + 1];
        const int a = __float2int_rn(__bfloat162float(v0.x)) & 0xff;
        const int b = __float2int_rn(__bfloat162float(v0.y)) & 0xff;
        const int c = __float2int_rn(__bfloat162float(v1.x)) & 0xff;
        const int d = __float2int_rn(__bfloat162float(v1.y)) & 0xff;
        dst[q] = a | (b << 8) | (c << 16) | (d << 24);
    }
}

// ============================================================================
// Kernel 1: per-row dynamic int8 quantization of x (proven)
// ============================================================================
__global__ __launch_bounds__(256) void quant_v2(const float* __restrict__ x) {
    __shared__ float smax[256];
    const int row = blockIdx.x;
    const int tid = threadIdx.x;
    const float* xr = x + (size_t)row * K_TOTAL;
    float v[16];
    float am = 0.0f;
#pragma unroll
    for (int t = 0; t < 16; t++) {
        v[t] = xr[tid + t * 256];
        am = fmaxf(am, fabsf(v[t]));
    }
    smax[tid] = am;
    __syncthreads();
#pragma unroll
    for (int off = 128; off > 0; off >>= 1) {
        if (tid < off) smax[tid] = fmaxf(smax[tid], smax[tid + off]);
        __syncthreads();
    }
    const float s = smax[0] / 127.0f;
    int8_t* q = g_xq + (size_t)row * K_TOTAL;
#pragma unroll
    for (int t = 0; t < 16; t++) q[tid + t * 256] = (int8_t)__float2int_rn(v[t] / s);
    if (tid == 0) g_sx[row] = s;
}

// ============================================================================
// Kernel 2: INTRA-CTA HYBRID GEMM.
//   warps 0-3 : IMMA engine (tensor pipe) on n 0..63   [unchanged from R13]
//   warps 4-7 : dp4a engine (fma pipe)    on n 64..127 [REWORKED:
//               K-transposed SMEM w/ bank swizzle -> LDS.128 fragment reads
//               (4 per kw instead of 16 scalar LDS), double-buffered with
//               register prefetch and ONE named barrier per K-slab]
// ============================================================================
#define BK 64
#define KW 16

__global__ __launch_bounds__(256, 2) void gemm_hybrid3(const float* __restrict__ SCB,
                                                       float* __restrict__ y) {
    __shared__ __align__(16) int8_t sIA[2][128 * BK];   // IMMA A: 2 x 8 KB
    __shared__ __align__(16) int8_t sIB[2][64 * BK];    // IMMA B: 2 x 4 KB
    __shared__ __align__(16) int    sDA[2][KW][128];    // dp4a A: 2 x 8 KB (K-transposed)
    __shared__ __align__(16) int    sDB[2][KW][64];     // dp4a B: 2 x 4 KB (K-transposed)

    const int tid = threadIdx.x;
    const int bn = blockIdx.x;     // 0..31
    const int bm = blockIdx.y;     // 0..63

    if (tid < 128) {
        // ==================== IMMA half: n 0..63 (verbatim R13) ====================
        const int wid = tid >> 5;          // 0..3
        const int lane = tid & 31;
        const int wm = wid >> 1;           // 0..1 -> m offset wm*64
        const int wn2 = wid & 1;           // 0..1 -> n offset wn2*32

        const int8_t* aG[4]; uint32_t aSo[4];
#pragma unroll
        for (int i = 0; i < 4; i++) {
            const int c = tid + i * 128;
            const int r = c >> 2, s = c & 3;
            aG[i] = g_xq + (size_t)(bm * 128 + r) * K_TOTAL + s * 16;
            aSo[i] = swoff(r, s * 16);
        }
        const int8_t* bG[2]; uint32_t bSo[2];
#pragma unroll
        for (int i = 0; i < 2; i++) {
            const int c = tid + i * 128;
            const int r = c >> 2, s = c & 3;
            bG[i] = g_cb + (size_t)(bn * 128 + r) * K_TOTAL + s * 16;
            bSo[i] = swoff(r, s * 16);
        }

        const uint32_t aSm = smem_u32(&sIA[0][0]);
        const uint32_t bSm = smem_u32(&sIB[0][0]);

        const int q = lane >> 3, lr = lane & 7;
        const int aRowL = wm * 64 + (q & 1) * 8 + lr;
        const int aKL   = (q >> 1) * 16;
        const int bRowL = wn2 * 32 + (q >> 1) * 8 + lr;
        const int bKL   = (q & 1) * 16;

        int acc[16][4];
#pragma unroll
        for (int f = 0; f < 16; f++)
#pragma unroll
            for (int r = 0; r < 4; r++) acc[f][r] = 0;

        int4 ra[4], rb[2];
#pragma unroll
        for (int i = 0; i < 4; i++) ra[i] = *reinterpret_cast<const int4*>(aG[i]);
#pragma unroll
        for (int i = 0; i < 2; i++) rb[i] = *reinterpret_cast<const int4*>(bG[i]);
#pragma unroll
        for (int i = 0; i < 4; i++) sts128(aSm + aSo[i], ra[i]);
#pragma unroll
        for (int i = 0; i < 2; i++) sts128(bSm + bSo[i], rb[i]);
        barx(1, 128);

        const int NT = K_TOTAL / BK;   // 64
        for (int kt = 0; kt < NT; kt++) {
            const int buf = kt & 1;
            if (kt + 1 < NT) {
#pragma unroll
                for (int i = 0; i < 4; i++)
                    ra[i] = *reinterpret_cast<const int4*>(aG[i] + (kt + 1) * BK);
#pragma unroll
                for (int i = 0; i < 2; i++)
                    rb[i] = *reinterpret_cast<const int4*>(bG[i] + (kt + 1) * BK);
            }
            const uint32_t aB = aSm + buf * (128 * BK);
            const uint32_t bB = bSm + buf * (64 * BK);

#pragma unroll
            for (int ks = 0; ks < 2; ks++) {
                uint32_t a[4][4], b[4][2];
#pragma unroll
                for (int fi = 0; fi < 4; fi++)
                    ldsm_x4(a[fi], aB + swoff(aRowL + fi * 16, aKL + ks * 32));
#pragma unroll
                for (int pr = 0; pr < 2; pr++) {
                    uint32_t t4[4];
                    ldsm_x4(t4, bB + swoff(bRowL + pr * 16, bKL + ks * 32));
                    b[pr * 2][0] = t4[0]; b[pr * 2][1] = t4[1];
                    b[pr * 2 + 1][0] = t4[2]; b[pr * 2 + 1][1] = t4[3];
                }
#pragma unroll
                for (int fi = 0; fi < 4; fi++)
#pragma unroll
                    for (int fj = 0; fj < 4; fj++)
                        mma_s8(acc[fi * 4 + fj], a[fi], b[fj]);
            }

            barx(1, 128);
            if (kt + 1 < NT) {
                const uint32_t aN = aSm + (buf ^ 1) * (128 * BK);
                const uint32_t bN = bSm + (buf ^ 1) * (64 * BK);
#pragma unroll
                for (int i = 0; i < 4; i++) sts128(aN + aSo[i], ra[i]);
#pragma unroll
                for (int i = 0; i < 2; i++) sts128(bN + bSo[i], rb[i]);
            }
            barx(1, 128);
        }

        const int g = lane >> 2, tg = lane & 3;
        float scb[8];
#pragma unroll
        for (int fj = 0; fj < 4; fj++) {
            const int n = bn * 128 + wn2 * 32 + fj * 8 + tg * 2;
            scb[fj * 2]     = SCB[n]     * (1.0f / 127.0f);
            scb[fj * 2 + 1] = SCB[n + 1] * (1.0f / 127.0f);
        }
#pragma unroll
        for (int fi = 0; fi < 4; fi++) {
#pragma unroll
            for (int h = 0; h < 2; h++) {
                const int m = bm * 128 + wm * 64 + fi * 16 + g + h * 8;
                const float sm = g_sx[m];
                float* yr = y + (size_t)m * N_TOTAL + bn * 128 + wn2 * 32;
#pragma unroll
                for (int fj = 0; fj < 4; fj++) {
                    const int* c = acc[fi * 4 + fj];
                    float2 o;
                    o.x = (float)c[h * 2]     * sm * scb[fj * 2];
                    o.y = (float)c[h * 2 + 1] * sm * scb[fj * 2 + 1];
                    *reinterpret_cast<float2*>(yr + fj * 8 + tg * 2) = o;
                }
            }
        }
    } else {
        // ==================== dp4a half: n 64..127 (REWORKED) ====================
        const int t = tid - 128;           // 0..127

        // producer mapping: A 512 16B-chunks (4/thr), B 256 (2/thr)
        const int8_t* aP[4]; int aRow[4], aSeg[4];
#pragma unroll
        for (int i = 0; i < 4; i++) {
            const int c = t + i * 128;
            aRow[i] = c >> 2; aSeg[i] = c & 3;
            aP[i] = g_xq + (size_t)(bm * 128 + aRow[i]) * K_TOTAL + aSeg[i] * 16;
        }
        const int8_t* bP[2]; int bRow[2], bSeg[2];
#pragma unroll
        for (int i = 0; i < 2; i++) {
            const int c = t + i * 128;
            bRow[i] = c >> 2; bSeg[i] = c & 3;
            bP[i] = g_cb + (size_t)(bn * 128 + 64 + bRow[i]) * K_TOTAL + bSeg[i] * 16;
        }
        // swizzled row indices (row ^ (seg<<3)) — conflict-free STS
        const int aRS[4] = { aRow[0] ^ (aSeg[0] << 3), aRow[1] ^ (aSeg[1] << 3),
                             aRow[2] ^ (aSeg[2] << 3), aRow[3] ^ (aSeg[3] << 3) };
        const int bRS[2] = { bRow[0] ^ (bSeg[0] << 3), bRow[1] ^ (bSeg[1] << 3) };

        int acc[8][8];
#pragma unroll
        for (int i = 0; i < 8; i++)
#pragma unroll
            for (int j = 0; j < 8; j++) acc[i][j] = 0;

        const int ty = t >> 3;    // 0..15 -> rows ty*8..+7
        const int tx = t & 7;     // 0..7  -> local cols tx*8..+7

        int4 av[4], bv[2];
        // preload kt=0 -> buffer 0
#pragma unroll
        for (int i = 0; i < 4; i++) av[i] = *reinterpret_cast<const int4*>(aP[i]);
#pragma unroll
        for (int i = 0; i < 2; i++) bv[i] = *reinterpret_cast<const int4*>(bP[i]);
#pragma unroll
        for (int i = 0; i < 4; i++) {
            sDA[0][aSeg[i] * 4 + 0][aRS[i]] = av[i].x;
            sDA[0][aSeg[i] * 4 + 1][aRS[i]] = av[i].y;
            sDA[0][aSeg[i] * 4 + 2][aRS[i]] = av[i].z;
            sDA[0][aSeg[i] * 4 + 3][aRS[i]] = av[i].w;
        }
#pragma unroll
        for (int i = 0; i < 2; i++) {
            sDB[0][bSeg[i] * 4 + 0][bRS[i]] = bv[i].x;
            sDB[0][bSeg[i] * 4 + 1][bRS[i]] = bv[i].y;
            sDB[0][bSeg[i] * 4 + 2][bRS[i]] = bv[i].z;
            sDB[0][bSeg[i] * 4 + 3][bRS[i]] = bv[i].w;
        }
        barx(2, 128);

        const int NT = K_TOTAL / BK;   // 64
        for (int kt = 0; kt < NT; kt++) {
            const int buf = kt & 1;
            if (kt + 1 < NT) {   // prefetch next slab into registers
#pragma unroll
                for (int i = 0; i < 4; i++)
                    av[i] = *reinterpret_cast<const int4*>(aP[i] + (kt + 1) * BK);
#pragma unroll
                for (int i = 0; i < 2; i++)
                    bv[i] = *reinterpret_cast<const int4*>(bP[i] + (kt + 1) * BK);
            }

            // compute current buffer: LDS.128 fragment reads
#pragma unroll
            for (int kw = 0; kw < KW; kw++) {
                const int sgrp = kw >> 2;
                const int* ap = &sDA[buf][kw][(ty ^ sgrp) << 3];
                const int* bp = &sDB[buf][kw][(tx ^ sgrp) << 3];
                const int4 a0 = *reinterpret_cast<const int4*>(ap);
                const int4 a1 = *reinterpret_cast<const int4*>(ap + 4);
                const int4 b0 = *reinterpret_cast<const int4*>(bp);
                const int4 b1 = *reinterpret_cast<const int4*>(bp + 4);
                const int a[8] = {a0.x, a0.y, a0.z, a0.w, a1.x, a1.y, a1.z, a1.w};
                const int b[8] = {b0.x, b0.y, b0.z, b0.w, b1.x, b1.y, b1.z, b1.w};
#pragma unroll
                for (int i = 0; i < 8; i++)
#pragma unroll
                    for (int j = 0; j < 8; j++)
                        acc[i][j] = __dp4a(a[i], b[j], acc[i][j]);
            }

            // store prefetched slab into the other buffer; one barrier per slab
            if (kt + 1 < NT) {
                const int nb = buf ^ 1;
#pragma unroll
                for (int i = 0; i < 4; i++) {
                    sDA[nb][aSeg[i] * 4 + 0][aRS[i]] = av[i].x;
                    sDA[nb][aSeg[i] * 4 + 1][aRS[i]] = av[i].y;
                    sDA[nb][aSeg[i] * 4 + 2][aRS[i]] = av[i].z;
                    sDA[nb][aSeg[i] * 4 + 3][aRS[i]] = av[i].w;
                }
#pragma unroll
                for (int i = 0; i < 2; i++) {
                    sDB[nb][bSeg[i] * 4 + 0][bRS[i]] = bv[i].x;
                    sDB[nb][bSeg[i] * 4 + 1][bRS[i]] = bv[i].y;
                    sDB[nb][bSeg[i] * 4 + 2][bRS[i]] = bv[i].z;
                    sDB[nb][bSeg[i] * 4 + 3][bRS[i]] = bv[i].w;
                }
                barx(2, 128);
            }
        }

        // epilogue
        const int m0 = bm * 128 + ty * 8;
        const int n0 = bn * 128 + 64 + tx * 8;
#pragma unroll
        for (int i = 0; i < 8; i++) {
            const float sm = g_sx[m0 + i];
            float* yr = y + (size_t)(m0 + i) * N_TOTAL;
#pragma unroll
            for (int j = 0; j < 8; j++) {
                yr[n0 + j] = ((float)acc[i][j] * sm) * (SCB[n0 + j] * (1.0f / 127.0f));
            }
        }
    }
}

// ============================================================================
// Launch. Inputs bound by element count:
//   x: 33,554,432   CB: 16,777,216 (dtype auto-detected)   SCB: 4,096
// ============================================================================
extern "C" void kernel_launch(void* const* d_in, const int* in_sizes, int n_in,
                              void* d_out, int out_size) {
    const float* x   = nullptr;
    const void*  CB  = nullptr;
    const float* SCB = nullptr;
    for (int i = 0; i < n_in; i++) {
        if (in_sizes[i] == 33554432)      x   = (const float*)d_in[i];
        else if (in_sizes[i] == 16777216) CB  = d_in[i];
        else if (in_sizes[i] == 4096)     SCB = (const float*)d_in[i];
    }
    float* y = (float*)d_out;

    detect_cb_kernel<<<1, 256>>>(CB);
    convert_cb_kernel<<<(N_TOTAL * K_TOTAL / 4) / 256, 256>>>(CB);
    quant_v2<<<M_TOTAL, 256>>>(x);
    dim3 grid(N_TOTAL / 128, M_TOTAL / 128);   // 32 x 64 = 2048 CTAs
    gemm_hybrid3<<<grid, 256>>>(SCB, y);
}

// round 16
// speedup vs baseline: 1.7178x; 1.0287x over previous
#include <cuda_runtime.h>
#include <cuda_bf16.h>
#include <cstdint>
#include <math.h>

// Fixed problem sizes
#define M_TOTAL 8192      // B*S = 4*2048
#define N_TOTAL 4096      // OUT
#define K_TOTAL 4096      // IN

// ---- device-global scratch (allocation-free) ----
__device__ __align__(16) int8_t g_xq[(size_t)M_TOTAL * K_TOTAL];  // quantized x
__device__ __align__(16) int8_t g_cb[(size_t)N_TOTAL * K_TOTAL];  // normalized int8 weights
__device__ float g_sx[M_TOTAL];                                   // per-row scale absmax/127
__device__ int   g_cb_mode;   // 0=int8 packed, 1=int32, 2=fp32, 3=bf16

// Work split inside each 128x128 tile: IMMA engine n 0..79, dp4a engine n 80..127
#define N_IMMA 80
#define N_DP4A 48

// ============================================================================
// Helpers (base-ISA only)
// ============================================================================
__device__ __forceinline__ uint32_t smem_u32(const void* p) {
    uint32_t a;
    asm("{ .reg .u64 t; cvta.to.shared.u64 t, %1; cvt.u32.u64 %0, t; }"
        : "=r"(a) : "l"(p));
    return a;
}
__device__ __forceinline__ void cp16(uint32_t dst, const void* src) {
    asm volatile("cp.async.cg.shared.global [%0], [%1], 16;" :: "r"(dst), "l"(src));
}
__device__ __forceinline__ void cp_commit() {
    asm volatile("cp.async.commit_group;" ::: "memory");
}
__device__ __forceinline__ void cp_wait0() {
    asm volatile("cp.async.wait_group 0;" ::: "memory");
}
__device__ __forceinline__ void ldsm_x4(uint32_t* r, uint32_t addr) {
    asm volatile("ldmatrix.sync.aligned.m8n8.x4.shared.b16 {%0,%1,%2,%3}, [%4];"
                 : "=r"(r[0]), "=r"(r[1]), "=r"(r[2]), "=r"(r[3]) : "r"(addr));
}
__device__ __forceinline__ void ldsm_x2(uint32_t& r0, uint32_t& r1, uint32_t addr) {
    asm volatile("ldmatrix.sync.aligned.m8n8.x2.shared.b16 {%0,%1}, [%2];"
                 : "=r"(r0), "=r"(r1) : "r"(addr));
}
__device__ __forceinline__ void mma_s8(int* c, const uint32_t* a, const uint32_t* b) {
    asm volatile("mma.sync.aligned.m16n8k32.row.col.s32.s8.s8.s32 "
                 "{%0,%1,%2,%3}, {%4,%5,%6,%7}, {%8,%9}, {%0,%1,%2,%3};"
                 : "+r"(c[0]), "+r"(c[1]), "+r"(c[2]), "+r"(c[3])
                 : "r"(a[0]), "r"(a[1]), "r"(a[2]), "r"(a[3]),
                   "r"(b[0]), "r"(b[1]));
}
__device__ __forceinline__ void barx(int id, int cnt) {
    asm volatile("bar.sync %0, %1;" :: "r"(id), "r"(cnt) : "memory");
}
// swizzled byte offset for [rows x 64B] tiles (proven in R11)
__device__ __forceinline__ uint32_t swoff(int row, int k) {
    return (uint32_t)(row * 64 + k) ^ (((((uint32_t)row) >> 1) & 7u) << 4);
}

// ============================================================================
// Kernel 0a: detect CB storage dtype (proven)
// ============================================================================
__global__ void detect_cb_kernel(const void* __restrict__ cb) {
    __shared__ int ok_i32, ok_f32, ok_bf16;
    if (threadIdx.x == 0) { ok_i32 = 1; ok_f32 = 1; ok_bf16 = 1; }
    __syncthreads();
    const int tid = threadIdx.x;
    bool my_i32 = true, my_f32 = true, my_bf16 = true;
#pragma unroll
    for (int t = 0; t < 16; t++) {
        const int idx = tid + t * 256;
        const int vi = ((const int*)cb)[idx];
        if (vi < -127 || vi > 127) my_i32 = false;
        const float vf = ((const float*)cb)[idx];
        if (!(isfinite(vf) && fabsf(vf) <= 127.0f && vf == rintf(vf))) my_f32 = false;
        const unsigned short h = ((const unsigned short*)cb)[idx];
        __nv_bfloat16 bh = *reinterpret_cast<const __nv_bfloat16*>(&h);
        const float vb = __bfloat162float(bh);
        if (!(isfinite(vb) && fabsf(vb) <= 127.0f && vb == rintf(vb))) my_bf16 = false;
    }
    if (!my_i32)  ok_i32 = 0;
    if (!my_f32)  ok_f32 = 0;
    if (!my_bf16) ok_bf16 = 0;
    __syncthreads();
    if (tid == 0) {
        int mode = 0;
        if      (ok_i32)  mode = 1;
        else if (ok_f32)  mode = 2;
        else if (ok_bf16) mode = 3;
        g_cb_mode = mode;
    }
}

// ============================================================================
// Kernel 0b: normalize CB into packed int8 (proven)
// ============================================================================
__global__ __launch_bounds__(256) void convert_cb_kernel(const void* __restrict__ cb) {
    const int mode = g_cb_mode;
    const size_t q = (size_t)blockIdx.x * 256 + threadIdx.x;
    int* dst = reinterpret_cast<int*>(g_cb);
    if (mode == 0) {
        dst[q] = ((const int*)cb)[q];
    } else if (mode == 1) {
        const int4 v = ((const int4*)cb)[q];
        dst[q] = (int)((unsigned)(v.x & 0xff) | ((unsigned)(v.y & 0xff) << 8) |
                       ((unsigned)(v.z & 0xff) << 16) | ((unsigned)(v.w & 0xff) << 24));
    } else if (mode == 2) {
        const float4 v = ((const float4*)cb)[q];
        const int a = __float2int_rn(v.x) & 0xff, b = __float2int_rn(v.y) & 0xff;
        const int c = __float2int_rn(v.z) & 0xff, d = __float2int_rn(v.w) & 0xff;
        dst[q] = a | (b << 8) | (c << 16) | (d << 24);
    } else {
        const __nv_bfloat162* p = reinterpret_cast<const __nv_bfloat162*>(cb);
        const __nv_bfloat162 v0 = p[q * 2], v1 = p[q * 2 + 1];
        const int a = __float2int_rn(__bfloat162float(v0.x)) & 0xff;
        const int b = __float2int_rn(__bfloat162float(v0.y)) & 0xff;
        const int c = __float2int_rn(__bfloat162float(v1.x)) & 0xff;
        const int d = __float2int_rn(__bfloat162float(v1.y)) & 0xff;
        dst[q] = a | (b << 8) | (c << 16) | (d << 24);
    }
}

// ============================================================================
// Kernel 1: per-row dynamic int8 quantization of x (proven)
// ============================================================================
__global__ __launch_bounds__(256) void quant_v2(const float* __restrict__ x) {
    __shared__ float smax[256];
    const int row = blockIdx.x;
    const int tid = threadIdx.x;
    const float* xr = x + (size_t)row * K_TOTAL;
    float v[16];
    float am = 0.0f;
#pragma unroll
    for (int t = 0; t < 16; t++) {
        v[t] = xr[tid + t * 256];
        am = fmaxf(am, fabsf(v[t]));
    }
    smax[tid] = am;
    __syncthreads();
#pragma unroll
    for (int off = 128; off > 0; off >>= 1) {
        if (tid < off) smax[tid] = fmaxf(smax[tid], smax[tid + off]);
        __syncthreads();
    }
    const float s = smax[0] / 127.0f;
    int8_t* q = g_xq + (size_t)row * K_TOTAL;
#pragma unroll
    for (int t = 0; t < 16; t++) q[tid + t * 256] = (int8_t)__float2int_rn(v[t] / s);
    if (tid == 0) g_sx[row] = s;
}

// ============================================================================
// Kernel 2: INTRA-CTA HYBRID GEMM, rebalanced 80/48.
//   warps 0-3 : IMMA (tensor pipe), n 0..79, warp tile 64x40, cp.async producer
//   warps 4-7 : dp4a (fma pipe),    n 80..127, 8x6 micro-tile, reg double-buffer
// Independent named barriers; disjoint SMEM.
// ============================================================================
#define BK 64
#define KW 16
#define DB_STRIDE 50   // sDB column stride (pad 48->50: conflict-free STS)

__global__ __launch_bounds__(256, 2) void gemm_hybrid4(const float* __restrict__ SCB,
                                                       float* __restrict__ y) {
    __shared__ __align__(16) int8_t sIA[2][128 * BK];       // IMMA A: 2 x 8 KB
    __shared__ __align__(16) int8_t sIB[2][N_IMMA * BK];    // IMMA B: 2 x 5 KB
    __shared__ __align__(16) int    sDA[2][KW][128];        // dp4a A: 2 x 8 KB
    __shared__ __align__(16) int    sDB[2][KW][DB_STRIDE];  // dp4a B: 2 x 3.2 KB

    const int tid = threadIdx.x;
    const int bn = blockIdx.x;     // 0..31
    const int bm = blockIdx.y;     // 0..63

    if (tid < 128) {
        // ==================== IMMA half: n 0..79 ====================
        const int wid = tid >> 5;          // 0..3
        const int lane = tid & 31;
        const int wm = wid >> 1;           // m offset wm*64
        const int wn2 = wid & 1;           // n offset wn2*40

        // cp.async producer mapping
        // A: 512 16B-chunks (4/thr)
        const int8_t* aSrc[4]; uint32_t aDst[4];
#pragma unroll
        for (int i = 0; i < 4; i++) {
            const int c = tid + i * 128;
            const int r = c >> 2, s = c & 3;
            aSrc[i] = g_xq + (size_t)(bm * 128 + r) * K_TOTAL + s * 16;
            aDst[i] = swoff(r, s * 16);
        }
        // B: 320 chunks (2/thr + third for tid<64)
        const int8_t* bSrc[3]; uint32_t bDst[3];
#pragma unroll
        for (int i = 0; i < 3; i++) {
            const int c = tid + i * 128;
            const int cc = (c < 320) ? c : 0;
            const int r = cc >> 2, s = cc & 3;
            bSrc[i] = g_cb + (size_t)(bn * 128 + r) * K_TOTAL + s * 16;
            bDst[i] = swoff(r, s * 16);
        }
        const bool hasB2 = (tid < 64);

        const uint32_t aSm = smem_u32(&sIA[0][0]);
        const uint32_t bSm = smem_u32(&sIB[0][0]);

        const int q = lane >> 3, lr = lane & 7;
        const int aRowL = wm * 64 + (q & 1) * 8 + lr;
        const int aKL   = (q >> 1) * 16;
        const int bRowL = wn2 * 40 + (q >> 1) * 8 + lr;      // x4 frags (fj 0..3)
        const int bKL   = (q & 1) * 16;
        const int l4 = lane & 15;                            // x2 frag (fj 4)
        const int b2Row = wn2 * 40 + 32 + (l4 & 7);
        const int b2K   = (l4 >> 3) * 16;

        int acc[20][4];
#pragma unroll
        for (int f = 0; f < 20; f++)
#pragma unroll
            for (int r = 0; r < 4; r++) acc[f][r] = 0;

        // preload slab 0 -> buffer 0
#pragma unroll
        for (int i = 0; i < 4; i++) cp16(aSm + aDst[i], aSrc[i]);
#pragma unroll
        for (int i = 0; i < 2; i++) cp16(bSm + bDst[i], bSrc[i]);
        if (hasB2) cp16(bSm + bDst[2], bSrc[2]);
        cp_commit(); cp_wait0();
        barx(1, 128);

        const int NT = K_TOTAL / BK;   // 64
        for (int kt = 0; kt < NT; kt++) {
            const int buf = kt & 1;
            if (kt + 1 < NT) {     // async-load next slab into other buffer
                const uint32_t aN = aSm + (buf ^ 1) * (128 * BK);
                const uint32_t bN = bSm + (buf ^ 1) * (N_IMMA * BK);
                const int off = (kt + 1) * BK;
#pragma unroll
                for (int i = 0; i < 4; i++) cp16(aN + aDst[i], aSrc[i] + off);
#pragma unroll
                for (int i = 0; i < 2; i++) cp16(bN + bDst[i], bSrc[i] + off);
                if (hasB2) cp16(bN + bDst[2], bSrc[2] + off);
                cp_commit();
            }
            const uint32_t aB = aSm + buf * (128 * BK);
            const uint32_t bB = bSm + buf * (N_IMMA * BK);

#pragma unroll
            for (int ks = 0; ks < 2; ks++) {
                uint32_t a[4][4], b[5][2];
#pragma unroll
                for (int fi = 0; fi < 4; fi++)
                    ldsm_x4(a[fi], aB + swoff(aRowL + fi * 16, aKL + ks * 32));
#pragma unroll
                for (int pr = 0; pr < 2; pr++) {
                    uint32_t t4[4];
                    ldsm_x4(t4, bB + swoff(bRowL + pr * 16, bKL + ks * 32));
                    b[pr * 2][0] = t4[0]; b[pr * 2][1] = t4[1];
                    b[pr * 2 + 1][0] = t4[2]; b[pr * 2 + 1][1] = t4[3];
                }
                ldsm_x2(b[4][0], b[4][1], bB + swoff(b2Row, b2K + ks * 32));
#pragma unroll
                for (int fi = 0; fi < 4; fi++)
#pragma unroll
                    for (int fj = 0; fj < 5; fj++)
                        mma_s8(acc[fi * 5 + fj], a[fi], b[fj]);
            }

            cp_wait0();
            barx(1, 128);
        }

        // epilogue
        const int g = lane >> 2, tg = lane & 3;
        float scb[10];
#pragma unroll
        for (int fj = 0; fj < 5; fj++) {
            const int n = bn * 128 + wn2 * 40 + fj * 8 + tg * 2;
            scb[fj * 2]     = SCB[n]     * (1.0f / 127.0f);
            scb[fj * 2 + 1] = SCB[n + 1] * (1.0f / 127.0f);
        }
#pragma unroll
        for (int fi = 0; fi < 4; fi++) {
#pragma unroll
            for (int h = 0; h < 2; h++) {
                const int m = bm * 128 + wm * 64 + fi * 16 + g + h * 8;
                const float sm = g_sx[m];
                float* yr = y + (size_t)m * N_TOTAL + bn * 128 + wn2 * 40;
#pragma unroll
                for (int fj = 0; fj < 5; fj++) {
                    const int* c = acc[fi * 5 + fj];
                    float2 o;
                    o.x = (float)c[h * 2]     * sm * scb[fj * 2];
                    o.y = (float)c[h * 2 + 1] * sm * scb[fj * 2 + 1];
                    *reinterpret_cast<float2*>(yr + fj * 8 + tg * 2) = o;
                }
            }
        }
    } else {
        // ==================== dp4a half: n 80..127 ====================
        const int t = tid - 128;           // 0..127

        // producer: A 512 chunks (4/thr), B 192 chunks (1/thr + second for t<64)
        const int8_t* aP[4]; int aRow[4], aSeg[4];
#pragma unroll
        for (int i = 0; i < 4; i++) {
            const int c = t + i * 128;
            aRow[i] = c >> 2; aSeg[i] = c & 3;
            aP[i] = g_xq + (size_t)(bm * 128 + aRow[i]) * K_TOTAL + aSeg[i] * 16;
        }
        const int8_t* bP[2]; int bRow[2], bSeg[2];
#pragma unroll
        for (int i = 0; i < 2; i++) {
            const int c = t + i * 128;
            const int cc = (c < 192) ? c : 0;
            bRow[i] = cc >> 2; bSeg[i] = cc & 3;
            bP[i] = g_cb + (size_t)(bn * 128 + 80 + bRow[i]) * K_TOTAL + bSeg[i] * 16;
        }
        const bool hasB1 = (t < 64);
        const int aRS[4] = { aRow[0] ^ (aSeg[0] << 3), aRow[1] ^ (aSeg[1] << 3),
                             aRow[2] ^ (aSeg[2] << 3), aRow[3] ^ (aSeg[3] << 3) };

        int acc[8][6];
#pragma unroll
        for (int i = 0; i < 8; i++)
#pragma unroll
            for (int j = 0; j < 6; j++) acc[i][j] = 0;

        const int ty = t >> 3;    // 0..15 -> rows ty*8..+7
        const int tx = t & 7;     // 0..7  -> local cols tx*6..+5

        int4 av[4], bv[2];
        // preload kt=0 -> buffer 0
#pragma unroll
        for (int i = 0; i < 4; i++) av[i] = *reinterpret_cast<const int4*>(aP[i]);
        bv[0] = *reinterpret_cast<const int4*>(bP[0]);
        if (hasB1) bv[1] = *reinterpret_cast<const int4*>(bP[1]);
#pragma unroll
        for (int i = 0; i < 4; i++) {
            sDA[0][aSeg[i] * 4 + 0][aRS[i]] = av[i].x;
            sDA[0][aSeg[i] * 4 + 1][aRS[i]] = av[i].y;
            sDA[0][aSeg[i] * 4 + 2][aRS[i]] = av[i].z;
            sDA[0][aSeg[i] * 4 + 3][aRS[i]] = av[i].w;
        }
        sDB[0][bSeg[0] * 4 + 0][bRow[0]] = bv[0].x;
        sDB[0][bSeg[0] * 4 + 1][bRow[0]] = bv[0].y;
        sDB[0][bSeg[0] * 4 + 2][bRow[0]] = bv[0].z;
        sDB[0][bSeg[0] * 4 + 3][bRow[0]] = bv[0].w;
        if (hasB1) {
            sDB[0][bSeg[1] * 4 + 0][bRow[1]] = bv[1].x;
            sDB[0][bSeg[1] * 4 + 1][bRow[1]] = bv[1].y;
            sDB[0][bSeg[1] * 4 + 2][bRow[1]] = bv[1].z;
            sDB[0][bSeg[1] * 4 + 3][bRow[1]] = bv[1].w;
        }
        barx(2, 128);

        const int NT = K_TOTAL / BK;   // 64
        for (int kt = 0; kt < NT; kt++) {
            const int buf = kt & 1;
            if (kt + 1 < NT) {   // register prefetch
#pragma unroll
                for (int i = 0; i < 4; i++)
                    av[i] = *reinterpret_cast<const int4*>(aP[i] + (kt + 1) * BK);
                bv[0] = *reinterpret_cast<const int4*>(bP[0] + (kt + 1) * BK);
                if (hasB1) bv[1] = *reinterpret_cast<const int4*>(bP[1] + (kt + 1) * BK);
            }

#pragma unroll
            for (int kw = 0; kw < KW; kw++) {
                const int sgrp = kw >> 2;
                const int* ap = &sDA[buf][kw][(ty ^ sgrp) << 3];
                const int4 a0 = *reinterpret_cast<const int4*>(ap);
                const int4 a1 = *reinterpret_cast<const int4*>(ap + 4);
                const int2* bp = reinterpret_cast<const int2*>(&sDB[buf][kw][tx * 6]);
                const int2 b01 = bp[0], b23 = bp[1], b45 = bp[2];
                const int a[8] = {a0.x, a0.y, a0.z, a0.w, a1.x, a1.y, a1.z, a1.w};
                const int b[6] = {b01.x, b01.y, b23.x, b23.y, b45.x, b45.y};
#pragma unroll
                for (int i = 0; i < 8; i++)
#pragma unroll
                    for (int j = 0; j < 6; j++)
                        acc[i][j] = __dp4a(a[i], b[j], acc[i][j]);
            }

            if (kt + 1 < NT) {
                const int nb = buf ^ 1;
#pragma unroll
                for (int i = 0; i < 4; i++) {
                    sDA[nb][aSeg[i] * 4 + 0][aRS[i]] = av[i].x;
                    sDA[nb][aSeg[i] * 4 + 1][aRS[i]] = av[i].y;
                    sDA[nb][aSeg[i] * 4 + 2][aRS[i]] = av[i].z;
                    sDA[nb][aSeg[i] * 4 + 3][aRS[i]] = av[i].w;
                }
                sDB[nb][bSeg[0] * 4 + 0][bRow[0]] = bv[0].x;
                sDB[nb][bSeg[0] * 4 + 1][bRow[0]] = bv[0].y;
                sDB[nb][bSeg[0] * 4 + 2][bRow[0]] = bv[0].z;
                sDB[nb][bSeg[0] * 4 + 3][bRow[0]] = bv[0].w;
                if (hasB1) {
                    sDB[nb][bSeg[1] * 4 + 0][bRow[1]] = bv[1].x;
                    sDB[nb][bSeg[1] * 4 + 1][bRow[1]] = bv[1].y;
                    sDB[nb][bSeg[1] * 4 + 2][bRow[1]] = bv[1].z;
                    sDB[nb][bSeg[1] * 4 + 3][bRow[1]] = bv[1].w;
                }
                barx(2, 128);
            }
        }

        // epilogue
        const int m0 = bm * 128 + ty * 8;
        const int n0 = bn * 128 + 80 + tx * 6;
        float scb[6];
#pragma unroll
        for (int j = 0; j < 6; j++) scb[j] = SCB[n0 + j] * (1.0f / 127.0f);
#pragma unroll
        for (int i = 0; i < 8; i++) {
            const float sm = g_sx[m0 + i];
            float* yr = y + (size_t)(m0 + i) * N_TOTAL + n0;
#pragma unroll
            for (int j = 0; j < 6; j += 2) {
                float2 o;
                o.x = (float)acc[i][j]     * sm * scb[j];
                o.y = (float)acc[i][j + 1] * sm * scb[j + 1];
                *reinterpret_cast<float2*>(yr + j) = o;
            }
        }
    }
}

// ============================================================================
// Launch. Inputs bound by element count:
//   x: 33,554,432   CB: 16,777,216 (dtype auto-detected)   SCB: 4,096
// ============================================================================
extern "C" void kernel_launch(void* const* d_in, const int* in_sizes, int n_in,
                              void* d_out, int out_size) {
    const float* x   = nullptr;
    const void*  CB  = nullptr;
    const float* SCB = nullptr;
    for (int i = 0; i < n_in; i++) {
        if (in_sizes[i] == 33554432)      x   = (const float*)d_in[i];
        else if (in_sizes[i] == 16777216) CB  = d_in[i];
        else if (in_sizes[i] == 4096)     SCB = (const float*)d_in[i];
    }
    float* y = (float*)d_out;

    detect_cb_kernel<<<1, 256>>>(CB);
    convert_cb_kernel<<<(N_TOTAL * K_TOTAL / 4) / 256, 256>>>(CB);
    quant_v2<<<M_TOTAL, 256>>>(x);
    dim3 grid(N_TOTAL / 128, M_TOTAL / 128);   // 32 x 64 = 2048 CTAs
    gemm_hybrid4<<<grid, 256>>>(SCB, y);
}